// round 11
// baseline (speedup 1.0000x reference)
#include <cuda_runtime.h>
#include <cuda_bf16.h>
#include <cuda_fp16.h>
#include <math.h>
#include <stdint.h>

#define BATCH  4096
#define IN_DIM 20000
#define H1DIM  512
#define H2DIM  256
#define NCAPS  32
#define PDIM   8
#define CDIM   16
#define NLAB   100

#define KP     20032            // IN_DIM padded to 313*64
#define NCH    313              // chunks
#define TILEB  16384            // one tile: 128 rows x 128 B (swizzled), contiguous
#define STGB   (4 * TILEB)      // stage: Ah, Al, Wh, Wl
#define NPRED  51200            // 32*100*16 per item

__device__ float g_h1[BATCH * H1DIM];
__device__ float g_h2[BATCH * H2DIM];
__device__ float g_prim[BATCH * NCAPS * PDIM];
__device__ __half g_pred[(size_t)BATCH * NPRED];
// tiled, pre-swizzled bf16 buffers
__device__ __align__(128) char g_Ahi[(size_t)32 * NCH * TILEB];
__device__ __align__(128) char g_Alo[(size_t)32 * NCH * TILEB];
__device__ __align__(128) char g_Whi[(size_t)4 * NCH * TILEB];
__device__ __align__(128) char g_Wlo[(size_t)4 * NCH * TILEB];

// ---------------- helpers ----------------
__device__ __forceinline__ uint32_t smem_u32(const void* p) {
    uint32_t a;
    asm("{ .reg .u64 t; cvta.to.shared.u64 t, %1; cvt.u32.u64 %0, t; }" : "=r"(a) : "l"(p));
    return a;
}
__device__ __forceinline__ uint32_t sw128(uint32_t off) {
    return off ^ ((off >> 3) & 0x70);
}
__device__ __forceinline__ void ldm_x4(uint32_t* r, uint32_t addr) {
    asm volatile("ldmatrix.sync.aligned.m8n8.x4.shared.b16 {%0,%1,%2,%3}, [%4];"
                 : "=r"(r[0]), "=r"(r[1]), "=r"(r[2]), "=r"(r[3]) : "r"(addr));
}
__device__ __forceinline__ void mma_bf16(float* c, const uint32_t* a, const uint32_t* b) {
    asm volatile("mma.sync.aligned.m16n8k16.row.col.f32.bf16.bf16.f32 "
                 "{%0,%1,%2,%3}, {%4,%5,%6,%7}, {%8,%9}, {%0,%1,%2,%3};"
                 : "+f"(c[0]), "+f"(c[1]), "+f"(c[2]), "+f"(c[3])
                 : "r"(a[0]), "r"(a[1]), "r"(a[2]), "r"(a[3]), "r"(b[0]), "r"(b[1]));
}
__device__ __forceinline__ uint32_t pack_bf2(__nv_bfloat16 a, __nv_bfloat16 b) {
    __nv_bfloat162 t; t.x = a; t.y = b;
    return *(uint32_t*)&t;
}
#define MBAR_INIT(a, c) asm volatile("mbarrier.init.shared.b64 [%0], %1;" :: "r"(a), "r"(c) : "memory")
#define MBAR_EXPECT_TX(a, b) asm volatile("mbarrier.arrive.expect_tx.shared.b64 _, [%0], %1;" :: "r"(a), "r"(b) : "memory")
#define BULK_G2S(dst, src, sz, mbar) \
    asm volatile("cp.async.bulk.shared::cluster.global.mbarrier::complete_tx::bytes [%0], [%1], %2, [%3];" \
                 :: "r"(dst), "l"(src), "r"(sz), "r"(mbar) : "memory")

#define MBAR_WAIT(mbar_smem_addr, phase_parity) do { \
    uint32_t _mbar = (uint32_t)(mbar_smem_addr); \
    uint32_t _parity = (uint32_t)(phase_parity); \
    uint32_t _done; \
    asm volatile( \
        "{\n\t.reg .pred p;\n\t" \
        "mbarrier.try_wait.parity.acquire.cta.shared::cta.b64 p, [%1], %2;\n\t" \
        "selp.b32 %0, 1, 0, p;\n\t}" \
        : "=r"(_done) : "r"(_mbar), "r"(_parity) : "memory"); \
    if (!_done) { \
        asm volatile( \
            "{\n\t.reg .pred P1;\n\t" \
            "WAIT_LOOP_%=:\n\t" \
            "mbarrier.try_wait.parity.acquire.cta.shared::cta.b64 P1, [%0], %1, 0x989680;\n\t" \
            "@P1 bra.uni WAIT_DONE_%=;\n\t" \
            "bra.uni WAIT_LOOP_%=;\n\t" \
            "WAIT_DONE_%=:\n\t}" \
            :: "r"(_mbar), "r"(_parity) : "memory"); \
    } \
} while(0)

// ---------------- prep: split features -> tiled swizzled bf16 hi/lo --------
__global__ void __launch_bounds__(256)
splitA(const float* __restrict__ F, char* __restrict__ Ah, char* __restrict__ Al) {
    int m = blockIdx.y;
    int u = blockIdx.x * 256 + threadIdx.x;        // 16B unit index, 0..2503
    if (u >= KP / 8) return;
    int k0 = u * 8;
    float v[8];
    if (k0 < IN_DIM) {
        const float4* fp = (const float4*)(F + (size_t)m * IN_DIM + k0);
        float4 f0 = fp[0], f1 = fp[1];
        v[0]=f0.x; v[1]=f0.y; v[2]=f0.z; v[3]=f0.w;
        v[4]=f1.x; v[5]=f1.y; v[6]=f1.z; v[7]=f1.w;
    } else {
#pragma unroll
        for (int j = 0; j < 8; j++) v[j] = 0.f;
    }
    uint32_t hi[4], lo[4];
#pragma unroll
    for (int j = 0; j < 4; j++) {
        float a = v[2*j], b = v[2*j+1];
        __nv_bfloat16 ha = __float2bfloat16(a), hb = __float2bfloat16(b);
        float la = a - __bfloat162float(ha), lb = b - __bfloat162float(hb);
        hi[j] = pack_bf2(ha, hb);
        lo[j] = pack_bf2(__float2bfloat16(la), __float2bfloat16(lb));
    }
    int mt = m >> 7, row = m & 127, ch = u >> 3, u8 = u & 7;
    uint32_t off = sw128((uint32_t)(row * 128 + u8 * 16));
    size_t addr = ((size_t)mt * NCH + ch) * TILEB + off;
    *(uint4*)(Ah + addr) = make_uint4(hi[0], hi[1], hi[2], hi[3]);
    *(uint4*)(Al + addr) = make_uint4(lo[0], lo[1], lo[2], lo[3]);
}

// ---------------- prep: transpose+split W1 [K,N] -> tiled swizzled ---------
__global__ void __launch_bounds__(256)
splitW(const float* __restrict__ W1, char* __restrict__ Wh, char* __restrict__ Wl) {
    __shared__ float ts[32][33];
    int k0 = blockIdx.x * 32, n0 = blockIdx.y * 32;
    int tx = threadIdx.x & 31, ty = threadIdx.x >> 5;
#pragma unroll
    for (int r = 0; r < 32; r += 8) {
        int k = k0 + ty + r;
        ts[ty + r][tx] = (k < IN_DIM) ? W1[(size_t)k * H1DIM + n0 + tx] : 0.f;
    }
    __syncthreads();
#pragma unroll
    for (int r = 0; r < 32; r += 8) {
        int n = n0 + ty + r;
        int k = k0 + tx;
        float x = ts[tx][ty + r];
        __nv_bfloat16 h = __float2bfloat16(x);
        float lo = x - __bfloat162float(h);
        int nt = n >> 7, row = n & 127, ch = k >> 6, kk = k & 63;
        uint32_t off = sw128((uint32_t)(row * 128 + kk * 2));
        size_t addr = ((size_t)nt * NCH + ch) * TILEB + off;
        *(__nv_bfloat16*)(Wh + addr) = h;
        *(__nv_bfloat16*)(Wl + addr) = __float2bfloat16(lo);
    }
}

// ---------------- GEMM1: 3-stage bulk-TMA + mma.sync bf16 (split hi/lo) ----
__global__ void __launch_bounds__(256)
gemm1_mma(const char* __restrict__ Ath, const char* __restrict__ Atl,
          const char* __restrict__ Wth, const char* __restrict__ Wtl,
          const float* __restrict__ bias, float* __restrict__ C) {
    extern __shared__ __align__(1024) char smem[];
    const uint32_t sb = smem_u32(smem);
    const uint32_t mb0 = sb, mb1 = sb + 8, mb2 = sb + 16;
    const uint32_t stage0 = sb + 1024;
    const int tid = threadIdx.x;
    const int lane = tid & 31, wid = tid >> 5;
    const int wm = wid & 3, wn = wid >> 2;
    const int m0 = blockIdx.y * 128, n0 = blockIdx.x * 128;

    const char* srcs[4] = {
        Ath + (size_t)blockIdx.y * NCH * TILEB,
        Atl + (size_t)blockIdx.y * NCH * TILEB,
        Wth + (size_t)blockIdx.x * NCH * TILEB,
        Wtl + (size_t)blockIdx.x * NCH * TILEB
    };

    if (tid == 0) { MBAR_INIT(mb0, 1u); MBAR_INIT(mb1, 1u); MBAR_INIT(mb2, 1u); }
    __syncthreads();

    const int aq = lane >> 3;
    const uint32_t a_row = (uint32_t)((aq & 1) * 8 + (lane & 7));
    const uint32_t a_colb = (uint32_t)((aq >> 1) * 16);
    const uint32_t b_row = (uint32_t)(((aq & 2) ? 8 : 0) + (lane & 7));
    const uint32_t b_colb = (uint32_t)((aq & 1) * 16);

    float acc[2][8][4];
#pragma unroll
    for (int mt = 0; mt < 2; mt++)
#pragma unroll
        for (int nt = 0; nt < 8; nt++)
#pragma unroll
            for (int e = 0; e < 4; e++) acc[mt][nt][e] = 0.f;

    if (tid == 0) {
#pragma unroll
        for (int c = 0; c < 2; c++) {
            uint32_t mbc = sb + 8u * c;
            MBAR_EXPECT_TX(mbc, (uint32_t)STGB);
#pragma unroll
            for (int p = 0; p < 4; p++)
                BULK_G2S(stage0 + c * STGB + p * TILEB, srcs[p] + (size_t)c * TILEB,
                         (uint32_t)TILEB, mbc);
        }
    }

    int s = 0, ph0 = 0, ph1 = 0, ph2v = 0;
    for (int t = 0; t < NCH; ++t) {
        if (t + 2 < NCH && tid == 0) {
            int s2 = s + 2; if (s2 >= 3) s2 -= 3;
            uint32_t mbn = sb + 8u * s2;
            uint32_t stn = stage0 + (uint32_t)(s2 * STGB);
            MBAR_EXPECT_TX(mbn, (uint32_t)STGB);
#pragma unroll
            for (int p = 0; p < 4; p++)
                BULK_G2S(stn + p * TILEB, srcs[p] + (size_t)(t + 2) * TILEB,
                         (uint32_t)TILEB, mbn);
        }
        if (s == 0)      { MBAR_WAIT(mb0, ph0); ph0 ^= 1; }
        else if (s == 1) { MBAR_WAIT(mb1, ph1); ph1 ^= 1; }
        else             { MBAR_WAIT(mb2, ph2v); ph2v ^= 1; }

        const uint32_t st = stage0 + (uint32_t)(s * STGB);
        const uint32_t aRow = (uint32_t)(wm * 32) + a_row;
        const uint32_t bRow = (uint32_t)(wn * 64) + b_row;

#pragma unroll
        for (int ks = 0; ks < 4; ++ks) {
            const uint32_t kb = (uint32_t)(ks * 32);
            uint32_t ah[2][4], al[2][4];
#pragma unroll
            for (int mt = 0; mt < 2; mt++) {
                uint32_t off = sw128((aRow + mt * 16) * 128 + kb + a_colb);
                ldm_x4(ah[mt], st + 0 * TILEB + off);
                ldm_x4(al[mt], st + 1 * TILEB + off);
            }
            uint32_t bh[8][2], bl[8][2];
#pragma unroll
            for (int np = 0; np < 4; np++) {
                uint32_t off = sw128((bRow + np * 16) * 128 + kb + b_colb);
                uint32_t rh[4], rl[4];
                ldm_x4(rh, st + 2 * TILEB + off);
                ldm_x4(rl, st + 3 * TILEB + off);
                bh[np * 2][0] = rh[0]; bh[np * 2][1] = rh[1];
                bh[np * 2 + 1][0] = rh[2]; bh[np * 2 + 1][1] = rh[3];
                bl[np * 2][0] = rl[0]; bl[np * 2][1] = rl[1];
                bl[np * 2 + 1][0] = rl[2]; bl[np * 2 + 1][1] = rl[3];
            }
#pragma unroll
            for (int mt = 0; mt < 2; mt++)
#pragma unroll
                for (int nt = 0; nt < 8; nt++) {
                    mma_bf16(acc[mt][nt], ah[mt], bh[nt]);
                    mma_bf16(acc[mt][nt], al[mt], bh[nt]);
                    mma_bf16(acc[mt][nt], ah[mt], bl[nt]);
                }
        }
        __syncthreads();
        s = (s + 1 == 3) ? 0 : s + 1;
    }

    const int l4 = lane >> 2, l2 = (lane & 3) * 2;
    const int ncol0 = n0 + wn * 64;
#pragma unroll
    for (int mt = 0; mt < 2; mt++) {
        int m = m0 + wm * 32 + mt * 16 + l4;
        float* r0 = C + (size_t)m * H1DIM + ncol0;
        float* r1 = r0 + (size_t)8 * H1DIM;
#pragma unroll
        for (int nt = 0; nt < 8; nt++) {
            int col = nt * 8 + l2;
            float b0 = bias[ncol0 + col], b1 = bias[ncol0 + col + 1];
            float v0 = fmaxf(acc[mt][nt][0] + b0, 0.f);
            float v1 = fmaxf(acc[mt][nt][1] + b1, 0.f);
            float v2 = fmaxf(acc[mt][nt][2] + b0, 0.f);
            float v3 = fmaxf(acc[mt][nt][3] + b1, 0.f);
            *(float2*)&r0[col] = make_float2(v0, v1);
            *(float2*)&r1[col] = make_float2(v2, v3);
        }
    }
}

// -------- f32x2 packed FMA helpers (GEMM2) --------
__device__ __forceinline__ unsigned long long dup2(float x) {
    unsigned long long r; asm("mov.b64 %0, {%1, %1};" : "=l"(r) : "f"(x)); return r;
}
__device__ __forceinline__ void fma2(unsigned long long& d, unsigned long long a, unsigned long long b) {
    asm("fma.rn.f32x2 %0, %1, %2, %0;" : "+l"(d) : "l"(a), "l"(b));
}
__device__ __forceinline__ void unp2(unsigned long long v, float& lo, float& hi) {
    asm("mov.b64 {%0, %1}, %2;" : "=f"(lo), "=f"(hi) : "l"(v));
}

// -------- GEMM (fp32): C = relu(A@B + bias), tiles 128x128x16 --------
__global__ void __launch_bounds__(256)
gemm_bias_relu(const float* __restrict__ A, const float* __restrict__ B,
               const float* __restrict__ bias, float* __restrict__ C,
               int M, int N, int K) {
    const int BM = 128, BKf = 16;
    __shared__ __align__(16) float As[2][16][132];
    __shared__ __align__(16) float Bs[2][16][128];

    const int tid = threadIdx.x;
    const int tx = tid & 15, ty = tid >> 4;
    const int m0 = blockIdx.y * BM, n0 = blockIdx.x * 128;
    const int ar0 = tid >> 2, ak0 = (tid & 3) * 4;
    const int br0 = tid >> 5, bc0 = (tid & 31) * 4;

    const float* Aptr = A + (size_t)(m0 + ar0) * K + ak0;
    const float* Bptr = B + (size_t)br0 * N + n0 + bc0;

    unsigned long long acc[8][4];
#pragma unroll
    for (int i = 0; i < 8; i++)
#pragma unroll
        for (int j = 0; j < 4; j++) acc[i][j] = 0ull;

    float4 a0f = *(const float4*)Aptr;
    float4 a1f = *(const float4*)(Aptr + (size_t)64 * K);
    float4 b0f = *(const float4*)Bptr;
    float4 b1f = *(const float4*)(Bptr + 8 * N);

    As[0][ak0+0][ar0] = a0f.x; As[0][ak0+1][ar0] = a0f.y;
    As[0][ak0+2][ar0] = a0f.z; As[0][ak0+3][ar0] = a0f.w;
    As[0][ak0+0][ar0+64] = a1f.x; As[0][ak0+1][ar0+64] = a1f.y;
    As[0][ak0+2][ar0+64] = a1f.z; As[0][ak0+3][ar0+64] = a1f.w;
    *(float4*)&Bs[0][br0][bc0] = b0f;
    *(float4*)&Bs[0][br0+8][bc0] = b1f;
    __syncthreads();

    const int nT = K / BKf;
    int buf = 0;
    for (int t = 0; t < nT; ++t) {
        if (t + 1 < nT) {
            const float* Ap = Aptr + (t + 1) * BKf;
            a0f = *(const float4*)Ap;
            a1f = *(const float4*)(Ap + (size_t)64 * K);
            const float* Bp = Bptr + (size_t)(t + 1) * BKf * N;
            b0f = *(const float4*)Bp;
            b1f = *(const float4*)(Bp + 8 * N);
        }
#pragma unroll
        for (int k = 0; k < BKf; ++k) {
            float4 av0 = *(const float4*)&As[buf][k][ty * 8];
            float4 av1 = *(const float4*)&As[buf][k][ty * 8 + 4];
            ulonglong2 bA = *(const ulonglong2*)&Bs[buf][k][tx * 8];
            ulonglong2 bB = *(const ulonglong2*)&Bs[buf][k][tx * 8 + 4];
            float av[8] = {av0.x, av0.y, av0.z, av0.w, av1.x, av1.y, av1.z, av1.w};
#pragma unroll
            for (int i = 0; i < 8; i++) {
                unsigned long long ad = dup2(av[i]);
                fma2(acc[i][0], ad, bA.x);
                fma2(acc[i][1], ad, bA.y);
                fma2(acc[i][2], ad, bB.x);
                fma2(acc[i][3], ad, bB.y);
            }
        }
        if (t + 1 < nT) {
            int nb = buf ^ 1;
            As[nb][ak0+0][ar0] = a0f.x; As[nb][ak0+1][ar0] = a0f.y;
            As[nb][ak0+2][ar0] = a0f.z; As[nb][ak0+3][ar0] = a0f.w;
            As[nb][ak0+0][ar0+64] = a1f.x; As[nb][ak0+1][ar0+64] = a1f.y;
            As[nb][ak0+2][ar0+64] = a1f.z; As[nb][ak0+3][ar0+64] = a1f.w;
            *(float4*)&Bs[nb][br0][bc0] = b0f;
            *(float4*)&Bs[nb][br0+8][bc0] = b1f;
        }
        __syncthreads();
        buf ^= 1;
    }

    float bb[8];
#pragma unroll
    for (int c = 0; c < 8; c++) bb[c] = bias[n0 + tx * 8 + c];
#pragma unroll
    for (int i = 0; i < 8; i++) {
        float* Crow = C + (size_t)(m0 + ty * 8 + i) * N + n0 + tx * 8;
#pragma unroll
        for (int j = 0; j < 4; j++) {
            float lo, hi; unp2(acc[i][j], lo, hi);
            lo = fmaxf(lo + bb[2*j], 0.f);
            hi = fmaxf(hi + bb[2*j+1], 0.f);
            *(float2*)&Crow[2*j] = make_float2(lo, hi);
        }
    }
}

// -------- LayerNorm over rows of 256, in place, warp per row --------
__global__ void __launch_bounds__(256)
ln_rows256(float* __restrict__ X, const float* __restrict__ g, const float* __restrict__ b) {
    int warp = threadIdx.x >> 5, lane = threadIdx.x & 31;
    int row = blockIdx.x * 8 + warp;
    float* xr = X + (size_t)row * 256;
    float x[8];
#pragma unroll
    for (int e = 0; e < 8; e++) x[e] = xr[lane + 32 * e];
    float s = 0.f;
#pragma unroll
    for (int e = 0; e < 8; e++) s += x[e];
#pragma unroll
    for (int o = 16; o; o >>= 1) s += __shfl_xor_sync(~0u, s, o);
    float mu = s * (1.f / 256.f);
    float vs = 0.f;
#pragma unroll
    for (int e = 0; e < 8; e++) { float d = x[e] - mu; vs += d * d; }
#pragma unroll
    for (int o = 16; o; o >>= 1) vs += __shfl_xor_sync(~0u, vs, o);
    float inv = rsqrtf(vs * (1.f / 256.f) + 1e-5f);
#pragma unroll
    for (int e = 0; e < 8; e++) {
        int c = lane + 32 * e;
        xr[c] = (x[e] - mu) * inv * g[c] + b[c];
    }
}

// -------- primary caps: einsum + bias + per-capsule LN over dim 8 --------
__global__ void __launch_bounds__(256)
prim_kernel(const float* __restrict__ h2, const float* __restrict__ pcW,
            const float* __restrict__ pcB, const float* __restrict__ pcG,
            const float* __restrict__ pcBeta, float* __restrict__ prim) {
    __shared__ float hs[8 * 256];
    int tid = threadIdx.x;
    int row0 = blockIdx.x * 8;
    for (int i = tid; i < 2048; i += 256) hs[i] = h2[(size_t)row0 * 256 + i];
    __syncthreads();

    int n = tid >> 3;
    float acc[8] = {0,0,0,0,0,0,0,0};
    const float* w = pcW + n * 2048 + (tid & 7);
    for (int c = 0; c < 256; c += 4) {
        float w0 = w[(c+0)*8], w1 = w[(c+1)*8], w2 = w[(c+2)*8], w3 = w[(c+3)*8];
#pragma unroll
        for (int r = 0; r < 8; r++)
            acc[r] += hs[r*256+c]*w0 + hs[r*256+c+1]*w1 + hs[r*256+c+2]*w2 + hs[r*256+c+3]*w3;
    }
    float bn = pcB[tid], gg = pcG[tid], bt = pcBeta[tid];
#pragma unroll
    for (int r = 0; r < 8; r++) {
        float x = acc[r] + bn;
        float s = x;
        s += __shfl_xor_sync(~0u, s, 1); s += __shfl_xor_sync(~0u, s, 2); s += __shfl_xor_sync(~0u, s, 4);
        float mu = s * 0.125f;
        float dv = x - mu;
        float v = dv * dv;
        v += __shfl_xor_sync(~0u, v, 1); v += __shfl_xor_sync(~0u, v, 2); v += __shfl_xor_sync(~0u, v, 4);
        float inv = rsqrtf(v * 0.125f + 1e-5f);
        prim[(size_t)(row0 + r) * 256 + tid] = dv * inv * gg + bt;
    }
}

// -------- predictions GEMM: pred[b][e] = dot8(prim[b][n], dcW[e]), fp16 out -
__global__ void __launch_bounds__(256)
pred_kernel(const float* __restrict__ prim, const float* __restrict__ dcW,
            __half* __restrict__ pred) {
    __shared__ float ps[16 * 256];
    const int tid = threadIdx.x;
    const int m0 = blockIdx.x * 16;
    for (int i = tid; i < 16 * 256 / 4; i += 256)
        ((float4*)ps)[i] = ((const float4*)(prim + (size_t)m0 * 256))[i];
    __syncthreads();

    for (int eg = 0; eg < 50; eg++) {
        int e4 = tid + eg * 256;
        int e = e4 * 4;
        int n = e / 1600;
        float4 w[8];
        const float4* wp = (const float4*)(dcW + (size_t)e * 8);
#pragma unroll
        for (int q = 0; q < 8; q++) w[q] = wp[q];
#pragma unroll 4
        for (int i = 0; i < 16; i++) {
            const float* p = ps + i * 256 + n * 8;
            float4 pa = *(const float4*)p;
            float4 pb = *(const float4*)(p + 4);
            float4 r;
            r.x = w[0].x*pa.x + w[0].y*pa.y + w[0].z*pa.z + w[0].w*pa.w
                + w[1].x*pb.x + w[1].y*pb.y + w[1].z*pb.z + w[1].w*pb.w;
            r.y = w[2].x*pa.x + w[2].y*pa.y + w[2].z*pa.z + w[2].w*pa.w
                + w[3].x*pb.x + w[3].y*pb.y + w[3].z*pb.z + w[3].w*pb.w;
            r.z = w[4].x*pa.x + w[4].y*pa.y + w[4].z*pa.z + w[4].w*pa.w
                + w[5].x*pb.x + w[5].y*pb.y + w[5].z*pb.z + w[5].w*pb.w;
            r.w = w[6].x*pa.x + w[6].y*pa.y + w[6].z*pa.z + w[6].w*pa.w
                + w[7].x*pb.x + w[7].y*pb.y + w[7].z*pb.z + w[7].w*pb.w;
            __half2 h0 = __floats2half2_rn(r.x, r.y);
            __half2 h1 = __floats2half2_rn(r.z, r.w);
            uint2 u;
            u.x = *(uint32_t*)&h0; u.y = *(uint32_t*)&h1;
            *(uint2*)(pred + (size_t)(m0 + i) * NPRED + e) = u;
        }
    }
}

// -------- fused routing + logits; fp16 pred via bulk copy ------------------
// smem: ph2[25600 half2] | b[3200] | c[3200] | vv[1600] | sp[128] | red[128] | mbar
__global__ void __launch_bounds__(1024)
routing_kernel(const __half* __restrict__ pred_g,
               const float* __restrict__ sf, const float* __restrict__ priors,
               const float* __restrict__ targets, const float* __restrict__ temp_p,
               float* __restrict__ out) {
    extern __shared__ float sm[];
    __half2* ph2 = (__half2*)sm;        // 25600 float slots
    float* bb   = sm + 25600;           // 3200 (persistent b-logits)
    float* cc   = bb + 3200;            // 3200 (softmax coupling)
    float* vv   = cc + 3200;            // 1600
    float* sp   = vv + 1600;            // 128
    float* red  = sp + 128;             // 128
    const uint32_t mbar = smem_u32(sm) + 33856u * 4u;

    const int bidx = blockIdx.x;
    const int tid = threadIdx.x;
    const int lane = tid & 31, warp = tid >> 5;

    if (tid == 0) MBAR_INIT(mbar, 1u);
    __syncthreads();
    if (tid == 0) {
        MBAR_EXPECT_TX(mbar, (uint32_t)(NPRED * 2));
        const char* src = (const char*)(pred_g + (size_t)bidx * NPRED);
        uint32_t dst = smem_u32(sm);
#pragma unroll
        for (int p = 0; p < 4; p++)
            BULK_G2S(dst + p * (NPRED / 2), src + (size_t)p * (NPRED / 2),
                     (uint32_t)(NPRED / 2), mbar);
    }

    if (tid < 100) red[tid] = fmaxf(sf[(size_t)bidx * 100 + tid], 0.f);
    __syncthreads();
    if (tid < 32) {
        float s = red[tid] + red[tid + 32] + red[tid + 64] + ((tid < 4) ? red[tid + 96] : 0.f);
#pragma unroll
        for (int o = 16; o; o >>= 1) s += __shfl_xor_sync(~0u, s, o);
        if (tid == 0) red[112] = s;
    }
    __syncthreads();
    float invs = 1.f / fmaxf(red[112], 1e-6f);
    __syncthreads();
    if (tid < 100) red[tid] = red[tid] * invs - 0.01f;
    __syncthreads();
    if (tid < 100) {
        float a = 0.f;
        for (int s = 0; s < 100; s++) a += red[s] * priors[s * 100 + tid];
        sp[tid] = a;
    }
    __syncthreads();

    for (int idx = tid; idx < 3200; idx += 1024) bb[idx] = sp[idx % 100] * 0.1f;

    MBAR_WAIT(mbar, 0);
    __syncthreads();

    for (int it = 0; it < 3; it++) {
        // softmax over j: warp n reads bb, writes cc
        {
            float b0 = bb[warp * 100 + lane];
            float b1 = bb[warp * 100 + 32 + lane];
            float b2 = bb[warp * 100 + 64 + lane];
            float b3 = (lane < 4) ? bb[warp * 100 + 96 + lane] : -1e30f;
            float m = fmaxf(fmaxf(b0, b1), fmaxf(b2, b3));
#pragma unroll
            for (int o = 16; o; o >>= 1) m = fmaxf(m, __shfl_xor_sync(~0u, m, o));
            float e0 = expf(b0 - m), e1 = expf(b1 - m), e2 = expf(b2 - m);
            float e3 = (lane < 4) ? expf(b3 - m) : 0.f;
            float s = e0 + e1 + e2 + e3;
#pragma unroll
            for (int o = 16; o; o >>= 1) s += __shfl_xor_sync(~0u, s, o);
            float is = 1.f / s;
            cc[warp * 100 + lane]      = e0 * is;
            cc[warp * 100 + 32 + lane] = e1 * is;
            cc[warp * 100 + 64 + lane] = e2 * is;
            if (lane < 4) cc[warp * 100 + 96 + lane] = e3 * is;
        }
        __syncthreads();

        // s[j,o-pair] over 800 half2 items
        if (tid < 800) {
            int j = tid >> 3;
            float s0 = 0.f, s1 = 0.f;
#pragma unroll 8
            for (int n = 0; n < 32; n++) {
                float c = cc[n * 100 + j];
                float2 p = __half22float2(ph2[n * 800 + tid]);
                s0 += c * p.x; s1 += c * p.y;
            }
            int o2 = (tid & 7) * 2;
            vv[j * 16 + o2] = s0;
            vv[j * 16 + o2 + 1] = s1;
        }
        __syncthreads();
        if (tid < 100) {
            float sq = 0.f;
#pragma unroll
            for (int o = 0; o < 16; o++) { float t = vv[tid * 16 + o]; sq += t * t; }
            red[tid] = (sq / (1.f + sq)) * rsqrtf(sq + 1e-8f);
        }
        __syncthreads();
        for (int idx = tid; idx < 1600; idx += 1024) vv[idx] *= red[idx >> 4];
        __syncthreads();

        if (it < 2) {
            float strength = 0.1f - 0.02f * (it + 1);
            // conflict-free: one (n,j,op) partial per lane, coalesced ph2 reads,
            // shfl-reduce over the 8-lane op group; lane op==0 commits.
#pragma unroll
            for (int k = 0; k < 25; k++) {
                int idx2 = tid + k * 1024;            // 0..25599
                int g = idx2 >> 3;                    // (n,j): n = g/100, j = g%100
                int op = idx2 & 7;                    // == tid & 7
                int j = g % 100;
                float2 p = __half22float2(ph2[idx2]);
                float2 v2 = *(const float2*)&vv[j * 16 + op * 2];
                float partial = p.x * v2.x + p.y * v2.y;
                partial += __shfl_xor_sync(~0u, partial, 1);
                partial += __shfl_xor_sync(~0u, partial, 2);
                partial += __shfl_xor_sync(~0u, partial, 4);
                if (op == 0) bb[g] += partial + sp[j] * strength;
            }
            __syncthreads();
        }
    }

    if (tid < 100) {
        float nr = 0.f, dt = 0.f;
#pragma unroll
        for (int o = 0; o < 16; o++) {
            float v = vv[tid * 16 + o];
            nr += v * v;
            dt += v * targets[tid * 16 + o];
        }
        out[(size_t)bidx * 100 + tid] = temp_p[0] * dt / fmaxf(sqrtf(nr), 1e-12f);
    }
}

extern "C" void kernel_launch(void* const* d_in, const int* in_sizes, int n_in,
                              void* d_out, int out_size) {
    const float* features = (const float*)d_in[0];
    const float* slot_f   = (const float*)d_in[1];
    const float* W1       = (const float*)d_in[2];
    const float* b1       = (const float*)d_in[3];
    const float* W2       = (const float*)d_in[4];
    const float* b2       = (const float*)d_in[5];
    const float* ln_g     = (const float*)d_in[6];
    const float* ln_b     = (const float*)d_in[7];
    const float* pc_W     = (const float*)d_in[8];
    const float* pc_b     = (const float*)d_in[9];
    const float* pc_g     = (const float*)d_in[10];
    const float* pc_beta  = (const float*)d_in[11];
    const float* dc_W     = (const float*)d_in[12];
    const float* priors   = (const float*)d_in[13];
    const float* targets  = (const float*)d_in[14];
    const float* temp     = (const float*)d_in[15];
    float* out = (float*)d_out;

    float* h1; cudaGetSymbolAddress((void**)&h1, g_h1);
    float* h2; cudaGetSymbolAddress((void**)&h2, g_h2);
    float* pr; cudaGetSymbolAddress((void**)&pr, g_prim);
    __half* pd; cudaGetSymbolAddress((void**)&pd, g_pred);
    char* Ah; cudaGetSymbolAddress((void**)&Ah, g_Ahi);
    char* Al; cudaGetSymbolAddress((void**)&Al, g_Alo);
    char* Wh; cudaGetSymbolAddress((void**)&Wh, g_Whi);
    char* Wl; cudaGetSymbolAddress((void**)&Wl, g_Wlo);

    const int RSMEM = 33856 * 4 + 32;     // 135456 B
    cudaFuncSetAttribute(routing_kernel, cudaFuncAttributeMaxDynamicSharedMemorySize, RSMEM);
    const int GSMEM = 1024 + 3 * STGB;    // 197632 B
    cudaFuncSetAttribute(gemm1_mma, cudaFuncAttributeMaxDynamicSharedMemorySize, GSMEM);

    splitA<<<dim3((KP / 8 + 255) / 256, BATCH), 256>>>(features, Ah, Al);
    splitW<<<dim3(KP / 32, H1DIM / 32), 256>>>(W1, Wh, Wl);
    gemm1_mma<<<dim3(H1DIM / 128, BATCH / 128), 256, GSMEM>>>(Ah, Al, Wh, Wl, b1, h1);
    gemm_bias_relu<<<dim3(256/128, 4096/128), 256>>>(h1, W2, b2, h2, 4096, 256, 512);
    ln_rows256<<<512, 256>>>(h2, ln_g, ln_b);
    prim_kernel<<<512, 256>>>(h2, pc_W, pc_b, pc_g, pc_beta, pr);
    pred_kernel<<<BATCH / 16, 256>>>(pr, dc_W, pd);
    routing_kernel<<<4096, 1024, RSMEM>>>(pd, slot_f, priors, targets, temp, out);
}

// round 12
// speedup vs baseline: 1.0415x; 1.0415x over previous
#include <cuda_runtime.h>
#include <cuda_bf16.h>
#include <cuda_fp16.h>
#include <math.h>
#include <stdint.h>

#define BATCH  4096
#define IN_DIM 20000
#define H1DIM  512
#define H2DIM  256
#define NCAPS  32
#define PDIM   8
#define CDIM   16
#define NLAB   100

#define KP     20032            // IN_DIM padded to 313*64
#define NCH    313              // chunks
#define TILEB  16384            // one tile: 128 rows x 128 B (swizzled), contiguous
#define STGB   (4 * TILEB)      // stage: Ah, Al, Wh, Wl
#define NPRED  51200            // 32*100*16 per item

__device__ float g_h1[BATCH * H1DIM];
__device__ float g_h2[BATCH * H2DIM];
__device__ float g_prim[BATCH * NCAPS * PDIM];
__device__ __half g_pred[(size_t)BATCH * NPRED];
// tiled, pre-swizzled bf16 buffers
__device__ __align__(128) char g_Ahi[(size_t)32 * NCH * TILEB];
__device__ __align__(128) char g_Alo[(size_t)32 * NCH * TILEB];
__device__ __align__(128) char g_Whi[(size_t)4 * NCH * TILEB];
__device__ __align__(128) char g_Wlo[(size_t)4 * NCH * TILEB];

// ---------------- helpers ----------------
__device__ __forceinline__ uint32_t smem_u32(const void* p) {
    uint32_t a;
    asm("{ .reg .u64 t; cvta.to.shared.u64 t, %1; cvt.u32.u64 %0, t; }" : "=r"(a) : "l"(p));
    return a;
}
__device__ __forceinline__ uint32_t sw128(uint32_t off) {
    return off ^ ((off >> 3) & 0x70);
}
__device__ __forceinline__ void ldm_x4(uint32_t* r, uint32_t addr) {
    asm volatile("ldmatrix.sync.aligned.m8n8.x4.shared.b16 {%0,%1,%2,%3}, [%4];"
                 : "=r"(r[0]), "=r"(r[1]), "=r"(r[2]), "=r"(r[3]) : "r"(addr));
}
__device__ __forceinline__ void mma_bf16(float* c, const uint32_t* a, const uint32_t* b) {
    asm volatile("mma.sync.aligned.m16n8k16.row.col.f32.bf16.bf16.f32 "
                 "{%0,%1,%2,%3}, {%4,%5,%6,%7}, {%8,%9}, {%0,%1,%2,%3};"
                 : "+f"(c[0]), "+f"(c[1]), "+f"(c[2]), "+f"(c[3])
                 : "r"(a[0]), "r"(a[1]), "r"(a[2]), "r"(a[3]), "r"(b[0]), "r"(b[1]));
}
__device__ __forceinline__ uint32_t pack_bf2(__nv_bfloat16 a, __nv_bfloat16 b) {
    __nv_bfloat162 t; t.x = a; t.y = b;
    return *(uint32_t*)&t;
}
#define MBAR_INIT(a, c) asm volatile("mbarrier.init.shared.b64 [%0], %1;" :: "r"(a), "r"(c) : "memory")
#define MBAR_EXPECT_TX(a, b) asm volatile("mbarrier.arrive.expect_tx.shared.b64 _, [%0], %1;" :: "r"(a), "r"(b) : "memory")
#define BULK_G2S(dst, src, sz, mbar) \
    asm volatile("cp.async.bulk.shared::cluster.global.mbarrier::complete_tx::bytes [%0], [%1], %2, [%3];" \
                 :: "r"(dst), "l"(src), "r"(sz), "r"(mbar) : "memory")

#define MBAR_WAIT(mbar_smem_addr, phase_parity) do { \
    uint32_t _mbar = (uint32_t)(mbar_smem_addr); \
    uint32_t _parity = (uint32_t)(phase_parity); \
    uint32_t _done; \
    asm volatile( \
        "{\n\t.reg .pred p;\n\t" \
        "mbarrier.try_wait.parity.acquire.cta.shared::cta.b64 p, [%1], %2;\n\t" \
        "selp.b32 %0, 1, 0, p;\n\t}" \
        : "=r"(_done) : "r"(_mbar), "r"(_parity) : "memory"); \
    if (!_done) { \
        asm volatile( \
            "{\n\t.reg .pred P1;\n\t" \
            "WAIT_LOOP_%=:\n\t" \
            "mbarrier.try_wait.parity.acquire.cta.shared::cta.b64 P1, [%0], %1, 0x989680;\n\t" \
            "@P1 bra.uni WAIT_DONE_%=;\n\t" \
            "bra.uni WAIT_LOOP_%=;\n\t" \
            "WAIT_DONE_%=:\n\t}" \
            :: "r"(_mbar), "r"(_parity) : "memory"); \
    } \
} while(0)

// ---------------- prep: split features -> tiled swizzled bf16 hi/lo --------
__global__ void __launch_bounds__(256)
splitA(const float* __restrict__ F, char* __restrict__ Ah, char* __restrict__ Al) {
    int m = blockIdx.y;
    int u = blockIdx.x * 256 + threadIdx.x;        // 16B unit index, 0..2503
    if (u >= KP / 8) return;
    int k0 = u * 8;
    float v[8];
    if (k0 < IN_DIM) {
        const float4* fp = (const float4*)(F + (size_t)m * IN_DIM + k0);
        float4 f0 = fp[0], f1 = fp[1];
        v[0]=f0.x; v[1]=f0.y; v[2]=f0.z; v[3]=f0.w;
        v[4]=f1.x; v[5]=f1.y; v[6]=f1.z; v[7]=f1.w;
    } else {
#pragma unroll
        for (int j = 0; j < 8; j++) v[j] = 0.f;
    }
    uint32_t hi[4], lo[4];
#pragma unroll
    for (int j = 0; j < 4; j++) {
        float a = v[2*j], b = v[2*j+1];
        __nv_bfloat16 ha = __float2bfloat16(a), hb = __float2bfloat16(b);
        float la = a - __bfloat162float(ha), lb = b - __bfloat162float(hb);
        hi[j] = pack_bf2(ha, hb);
        lo[j] = pack_bf2(__float2bfloat16(la), __float2bfloat16(lb));
    }
    int mt = m >> 7, row = m & 127, ch = u >> 3, u8 = u & 7;
    uint32_t off = sw128((uint32_t)(row * 128 + u8 * 16));
    size_t addr = ((size_t)mt * NCH + ch) * TILEB + off;
    *(uint4*)(Ah + addr) = make_uint4(hi[0], hi[1], hi[2], hi[3]);
    *(uint4*)(Al + addr) = make_uint4(lo[0], lo[1], lo[2], lo[3]);
}

// ---------------- prep: transpose+split W1 [K,N] -> tiled swizzled ---------
__global__ void __launch_bounds__(256)
splitW(const float* __restrict__ W1, char* __restrict__ Wh, char* __restrict__ Wl) {
    __shared__ float ts[32][33];
    int k0 = blockIdx.x * 32, n0 = blockIdx.y * 32;
    int tx = threadIdx.x & 31, ty = threadIdx.x >> 5;
#pragma unroll
    for (int r = 0; r < 32; r += 8) {
        int k = k0 + ty + r;
        ts[ty + r][tx] = (k < IN_DIM) ? W1[(size_t)k * H1DIM + n0 + tx] : 0.f;
    }
    __syncthreads();
#pragma unroll
    for (int r = 0; r < 32; r += 8) {
        int n = n0 + ty + r;
        int k = k0 + tx;
        float x = ts[tx][ty + r];
        __nv_bfloat16 h = __float2bfloat16(x);
        float lo = x - __bfloat162float(h);
        int nt = n >> 7, row = n & 127, ch = k >> 6, kk = k & 63;
        uint32_t off = sw128((uint32_t)(row * 128 + kk * 2));
        size_t addr = ((size_t)nt * NCH + ch) * TILEB + off;
        *(__nv_bfloat16*)(Wh + addr) = h;
        *(__nv_bfloat16*)(Wl + addr) = __float2bfloat16(lo);
    }
}

// ---------------- GEMM1: 3-stage bulk-TMA + mma.sync bf16 (split hi/lo) ----
__global__ void __launch_bounds__(256)
gemm1_mma(const char* __restrict__ Ath, const char* __restrict__ Atl,
          const char* __restrict__ Wth, const char* __restrict__ Wtl,
          const float* __restrict__ bias, float* __restrict__ C) {
    extern __shared__ __align__(1024) char smem[];
    const uint32_t sb = smem_u32(smem);
    const uint32_t mb0 = sb, mb1 = sb + 8, mb2 = sb + 16;
    const uint32_t stage0 = sb + 1024;
    const int tid = threadIdx.x;
    const int lane = tid & 31, wid = tid >> 5;
    const int wm = wid & 3, wn = wid >> 2;
    const int m0 = blockIdx.y * 128, n0 = blockIdx.x * 128;

    const char* srcs[4] = {
        Ath + (size_t)blockIdx.y * NCH * TILEB,
        Atl + (size_t)blockIdx.y * NCH * TILEB,
        Wth + (size_t)blockIdx.x * NCH * TILEB,
        Wtl + (size_t)blockIdx.x * NCH * TILEB
    };

    if (tid == 0) { MBAR_INIT(mb0, 1u); MBAR_INIT(mb1, 1u); MBAR_INIT(mb2, 1u); }
    __syncthreads();

    const int aq = lane >> 3;
    const uint32_t a_row = (uint32_t)((aq & 1) * 8 + (lane & 7));
    const uint32_t a_colb = (uint32_t)((aq >> 1) * 16);
    const uint32_t b_row = (uint32_t)(((aq & 2) ? 8 : 0) + (lane & 7));
    const uint32_t b_colb = (uint32_t)((aq & 1) * 16);

    float acc[2][8][4];
#pragma unroll
    for (int mt = 0; mt < 2; mt++)
#pragma unroll
        for (int nt = 0; nt < 8; nt++)
#pragma unroll
            for (int e = 0; e < 4; e++) acc[mt][nt][e] = 0.f;

    if (tid == 0) {
#pragma unroll
        for (int c = 0; c < 2; c++) {
            uint32_t mbc = sb + 8u * c;
            MBAR_EXPECT_TX(mbc, (uint32_t)STGB);
#pragma unroll
            for (int p = 0; p < 4; p++)
                BULK_G2S(stage0 + c * STGB + p * TILEB, srcs[p] + (size_t)c * TILEB,
                         (uint32_t)TILEB, mbc);
        }
    }

    int s = 0, ph0 = 0, ph1 = 0, ph2v = 0;
    for (int t = 0; t < NCH; ++t) {
        if (t + 2 < NCH && tid == 0) {
            int s2 = s + 2; if (s2 >= 3) s2 -= 3;
            uint32_t mbn = sb + 8u * s2;
            uint32_t stn = stage0 + (uint32_t)(s2 * STGB);
            MBAR_EXPECT_TX(mbn, (uint32_t)STGB);
#pragma unroll
            for (int p = 0; p < 4; p++)
                BULK_G2S(stn + p * TILEB, srcs[p] + (size_t)(t + 2) * TILEB,
                         (uint32_t)TILEB, mbn);
        }
        if (s == 0)      { MBAR_WAIT(mb0, ph0); ph0 ^= 1; }
        else if (s == 1) { MBAR_WAIT(mb1, ph1); ph1 ^= 1; }
        else             { MBAR_WAIT(mb2, ph2v); ph2v ^= 1; }

        const uint32_t st = stage0 + (uint32_t)(s * STGB);
        const uint32_t aRow = (uint32_t)(wm * 32) + a_row;
        const uint32_t bRow = (uint32_t)(wn * 64) + b_row;

#pragma unroll
        for (int ks = 0; ks < 4; ++ks) {
            const uint32_t kb = (uint32_t)(ks * 32);
            uint32_t ah[2][4], al[2][4];
#pragma unroll
            for (int mt = 0; mt < 2; mt++) {
                uint32_t off = sw128((aRow + mt * 16) * 128 + kb + a_colb);
                ldm_x4(ah[mt], st + 0 * TILEB + off);
                ldm_x4(al[mt], st + 1 * TILEB + off);
            }
            uint32_t bh[8][2], bl[8][2];
#pragma unroll
            for (int np = 0; np < 4; np++) {
                uint32_t off = sw128((bRow + np * 16) * 128 + kb + b_colb);
                uint32_t rh[4], rl[4];
                ldm_x4(rh, st + 2 * TILEB + off);
                ldm_x4(rl, st + 3 * TILEB + off);
                bh[np * 2][0] = rh[0]; bh[np * 2][1] = rh[1];
                bh[np * 2 + 1][0] = rh[2]; bh[np * 2 + 1][1] = rh[3];
                bl[np * 2][0] = rl[0]; bl[np * 2][1] = rl[1];
                bl[np * 2 + 1][0] = rl[2]; bl[np * 2 + 1][1] = rl[3];
            }
#pragma unroll
            for (int mt = 0; mt < 2; mt++)
#pragma unroll
                for (int nt = 0; nt < 8; nt++) {
                    mma_bf16(acc[mt][nt], ah[mt], bh[nt]);
                    mma_bf16(acc[mt][nt], al[mt], bh[nt]);
                    mma_bf16(acc[mt][nt], ah[mt], bl[nt]);
                }
        }
        __syncthreads();
        s = (s + 1 == 3) ? 0 : s + 1;
    }

    const int l4 = lane >> 2, l2 = (lane & 3) * 2;
    const int ncol0 = n0 + wn * 64;
#pragma unroll
    for (int mt = 0; mt < 2; mt++) {
        int m = m0 + wm * 32 + mt * 16 + l4;
        float* r0 = C + (size_t)m * H1DIM + ncol0;
        float* r1 = r0 + (size_t)8 * H1DIM;
#pragma unroll
        for (int nt = 0; nt < 8; nt++) {
            int col = nt * 8 + l2;
            float b0 = bias[ncol0 + col], b1 = bias[ncol0 + col + 1];
            float v0 = fmaxf(acc[mt][nt][0] + b0, 0.f);
            float v1 = fmaxf(acc[mt][nt][1] + b1, 0.f);
            float v2 = fmaxf(acc[mt][nt][2] + b0, 0.f);
            float v3 = fmaxf(acc[mt][nt][3] + b1, 0.f);
            *(float2*)&r0[col] = make_float2(v0, v1);
            *(float2*)&r1[col] = make_float2(v2, v3);
        }
    }
}

// -------- f32x2 packed FMA helpers (GEMM2) --------
__device__ __forceinline__ unsigned long long dup2(float x) {
    unsigned long long r; asm("mov.b64 %0, {%1, %1};" : "=l"(r) : "f"(x)); return r;
}
__device__ __forceinline__ void fma2(unsigned long long& d, unsigned long long a, unsigned long long b) {
    asm("fma.rn.f32x2 %0, %1, %2, %0;" : "+l"(d) : "l"(a), "l"(b));
}
__device__ __forceinline__ void unp2(unsigned long long v, float& lo, float& hi) {
    asm("mov.b64 {%0, %1}, %2;" : "=f"(lo), "=f"(hi) : "l"(v));
}

// -------- GEMM (fp32): C = relu(A@B + bias), tiles 128x128x16 --------
__global__ void __launch_bounds__(256)
gemm_bias_relu(const float* __restrict__ A, const float* __restrict__ B,
               const float* __restrict__ bias, float* __restrict__ C,
               int M, int N, int K) {
    const int BM = 128, BKf = 16;
    __shared__ __align__(16) float As[2][16][132];
    __shared__ __align__(16) float Bs[2][16][128];

    const int tid = threadIdx.x;
    const int tx = tid & 15, ty = tid >> 4;
    const int m0 = blockIdx.y * BM, n0 = blockIdx.x * 128;
    const int ar0 = tid >> 2, ak0 = (tid & 3) * 4;
    const int br0 = tid >> 5, bc0 = (tid & 31) * 4;

    const float* Aptr = A + (size_t)(m0 + ar0) * K + ak0;
    const float* Bptr = B + (size_t)br0 * N + n0 + bc0;

    unsigned long long acc[8][4];
#pragma unroll
    for (int i = 0; i < 8; i++)
#pragma unroll
        for (int j = 0; j < 4; j++) acc[i][j] = 0ull;

    float4 a0f = *(const float4*)Aptr;
    float4 a1f = *(const float4*)(Aptr + (size_t)64 * K);
    float4 b0f = *(const float4*)Bptr;
    float4 b1f = *(const float4*)(Bptr + 8 * N);

    As[0][ak0+0][ar0] = a0f.x; As[0][ak0+1][ar0] = a0f.y;
    As[0][ak0+2][ar0] = a0f.z; As[0][ak0+3][ar0] = a0f.w;
    As[0][ak0+0][ar0+64] = a1f.x; As[0][ak0+1][ar0+64] = a1f.y;
    As[0][ak0+2][ar0+64] = a1f.z; As[0][ak0+3][ar0+64] = a1f.w;
    *(float4*)&Bs[0][br0][bc0] = b0f;
    *(float4*)&Bs[0][br0+8][bc0] = b1f;
    __syncthreads();

    const int nT = K / BKf;
    int buf = 0;
    for (int t = 0; t < nT; ++t) {
        if (t + 1 < nT) {
            const float* Ap = Aptr + (t + 1) * BKf;
            a0f = *(const float4*)Ap;
            a1f = *(const float4*)(Ap + (size_t)64 * K);
            const float* Bp = Bptr + (size_t)(t + 1) * BKf * N;
            b0f = *(const float4*)Bp;
            b1f = *(const float4*)(Bp + 8 * N);
        }
#pragma unroll
        for (int k = 0; k < BKf; ++k) {
            float4 av0 = *(const float4*)&As[buf][k][ty * 8];
            float4 av1 = *(const float4*)&As[buf][k][ty * 8 + 4];
            ulonglong2 bA = *(const ulonglong2*)&Bs[buf][k][tx * 8];
            ulonglong2 bB = *(const ulonglong2*)&Bs[buf][k][tx * 8 + 4];
            float av[8] = {av0.x, av0.y, av0.z, av0.w, av1.x, av1.y, av1.z, av1.w};
#pragma unroll
            for (int i = 0; i < 8; i++) {
                unsigned long long ad = dup2(av[i]);
                fma2(acc[i][0], ad, bA.x);
                fma2(acc[i][1], ad, bA.y);
                fma2(acc[i][2], ad, bB.x);
                fma2(acc[i][3], ad, bB.y);
            }
        }
        if (t + 1 < nT) {
            int nb = buf ^ 1;
            As[nb][ak0+0][ar0] = a0f.x; As[nb][ak0+1][ar0] = a0f.y;
            As[nb][ak0+2][ar0] = a0f.z; As[nb][ak0+3][ar0] = a0f.w;
            As[nb][ak0+0][ar0+64] = a1f.x; As[nb][ak0+1][ar0+64] = a1f.y;
            As[nb][ak0+2][ar0+64] = a1f.z; As[nb][ak0+3][ar0+64] = a1f.w;
            *(float4*)&Bs[nb][br0][bc0] = b0f;
            *(float4*)&Bs[nb][br0+8][bc0] = b1f;
        }
        __syncthreads();
        buf ^= 1;
    }

    float bb[8];
#pragma unroll
    for (int c = 0; c < 8; c++) bb[c] = bias[n0 + tx * 8 + c];
#pragma unroll
    for (int i = 0; i < 8; i++) {
        float* Crow = C + (size_t)(m0 + ty * 8 + i) * N + n0 + tx * 8;
#pragma unroll
        for (int j = 0; j < 4; j++) {
            float lo, hi; unp2(acc[i][j], lo, hi);
            lo = fmaxf(lo + bb[2*j], 0.f);
            hi = fmaxf(hi + bb[2*j+1], 0.f);
            *(float2*)&Crow[2*j] = make_float2(lo, hi);
        }
    }
}

// -------- primary caps: fused row-LN + einsum + bias + per-capsule LN ------
__global__ void __launch_bounds__(256)
prim_kernel(const float* __restrict__ h2, const float* __restrict__ lng,
            const float* __restrict__ lnb, const float* __restrict__ pcW,
            const float* __restrict__ pcB, const float* __restrict__ pcG,
            const float* __restrict__ pcBeta, float* __restrict__ prim) {
    __shared__ float hs[8 * 256];
    int tid = threadIdx.x;
    int row0 = blockIdx.x * 8;
    for (int i = tid; i < 2048; i += 256) hs[i] = h2[(size_t)row0 * 256 + i];
    __syncthreads();

    // fused LayerNorm: warp per row (8 warps)
    {
        int warp = tid >> 5, lane = tid & 31;
        float* xr = hs + warp * 256;
        float x[8];
#pragma unroll
        for (int e = 0; e < 8; e++) x[e] = xr[lane + 32 * e];
        float s = 0.f;
#pragma unroll
        for (int e = 0; e < 8; e++) s += x[e];
#pragma unroll
        for (int o = 16; o; o >>= 1) s += __shfl_xor_sync(~0u, s, o);
        float mu = s * (1.f / 256.f);
        float vs = 0.f;
#pragma unroll
        for (int e = 0; e < 8; e++) { float d = x[e] - mu; vs += d * d; }
#pragma unroll
        for (int o = 16; o; o >>= 1) vs += __shfl_xor_sync(~0u, vs, o);
        float inv = rsqrtf(vs * (1.f / 256.f) + 1e-5f);
#pragma unroll
        for (int e = 0; e < 8; e++) {
            int c = lane + 32 * e;
            xr[c] = (x[e] - mu) * inv * lng[c] + lnb[c];
        }
    }
    __syncthreads();

    int n = tid >> 3;
    float acc[8] = {0,0,0,0,0,0,0,0};
    const float* w = pcW + n * 2048 + (tid & 7);
    for (int c = 0; c < 256; c += 4) {
        float w0 = w[(c+0)*8], w1 = w[(c+1)*8], w2 = w[(c+2)*8], w3 = w[(c+3)*8];
#pragma unroll
        for (int r = 0; r < 8; r++)
            acc[r] += hs[r*256+c]*w0 + hs[r*256+c+1]*w1 + hs[r*256+c+2]*w2 + hs[r*256+c+3]*w3;
    }
    float bn = pcB[tid], gg = pcG[tid], bt = pcBeta[tid];
#pragma unroll
    for (int r = 0; r < 8; r++) {
        float x = acc[r] + bn;
        float s = x;
        s += __shfl_xor_sync(~0u, s, 1); s += __shfl_xor_sync(~0u, s, 2); s += __shfl_xor_sync(~0u, s, 4);
        float mu = s * 0.125f;
        float dv = x - mu;
        float v = dv * dv;
        v += __shfl_xor_sync(~0u, v, 1); v += __shfl_xor_sync(~0u, v, 2); v += __shfl_xor_sync(~0u, v, 4);
        float inv = rsqrtf(v * 0.125f + 1e-5f);
        prim[(size_t)(row0 + r) * 256 + tid] = dv * inv * gg + bt;
    }
}

// -------- predictions GEMM: 32 items/CTA, fp16 out -------------------------
__global__ void __launch_bounds__(256)
pred_kernel(const float* __restrict__ prim, const float* __restrict__ dcW,
            __half* __restrict__ pred) {
    __shared__ float ps[32 * 256];
    const int tid = threadIdx.x;
    const int m0 = blockIdx.x * 32;
    for (int i = tid; i < 32 * 256 / 4; i += 256)
        ((float4*)ps)[i] = ((const float4*)(prim + (size_t)m0 * 256))[i];
    __syncthreads();

    for (int eg = 0; eg < 50; eg++) {
        int e4 = tid + eg * 256;
        int e = e4 * 4;
        int n = e / 1600;
        float4 w[8];
        const float4* wp = (const float4*)(dcW + (size_t)e * 8);
#pragma unroll
        for (int q = 0; q < 8; q++) w[q] = wp[q];
#pragma unroll 4
        for (int i = 0; i < 32; i++) {
            const float* p = ps + i * 256 + n * 8;
            float4 pa = *(const float4*)p;
            float4 pb = *(const float4*)(p + 4);
            float4 r;
            r.x = w[0].x*pa.x + w[0].y*pa.y + w[0].z*pa.z + w[0].w*pa.w
                + w[1].x*pb.x + w[1].y*pb.y + w[1].z*pb.z + w[1].w*pb.w;
            r.y = w[2].x*pa.x + w[2].y*pa.y + w[2].z*pa.z + w[2].w*pa.w
                + w[3].x*pb.x + w[3].y*pb.y + w[3].z*pb.z + w[3].w*pb.w;
            r.z = w[4].x*pa.x + w[4].y*pa.y + w[4].z*pa.z + w[4].w*pa.w
                + w[5].x*pb.x + w[5].y*pb.y + w[5].z*pb.z + w[5].w*pb.w;
            r.w = w[6].x*pa.x + w[6].y*pa.y + w[6].z*pa.z + w[6].w*pa.w
                + w[7].x*pb.x + w[7].y*pb.y + w[7].z*pb.z + w[7].w*pb.w;
            __half2 h0 = __floats2half2_rn(r.x, r.y);
            __half2 h1 = __floats2half2_rn(r.z, r.w);
            uint2 u;
            u.x = *(uint32_t*)&h0; u.y = *(uint32_t*)&h1;
            *(uint2*)(pred + (size_t)(m0 + i) * NPRED + e) = u;
        }
    }
}

// -------- fused routing + logits; fp16 pred via bulk copy (R10 version) ----
__global__ void __launch_bounds__(1024)
routing_kernel(const __half* __restrict__ pred_g,
               const float* __restrict__ sf, const float* __restrict__ priors,
               const float* __restrict__ targets, const float* __restrict__ temp_p,
               float* __restrict__ out) {
    extern __shared__ float sm[];
    __half2* ph2 = (__half2*)sm;        // 25600 half2 = 25600 float slots
    float* bq   = sm + 25600;           // 3200
    float* vv   = bq + 3200;            // 1600
    float* sp   = vv + 1600;            // 128
    float* mrow = sp + 128;             // 32
    float* lse  = mrow + 32;            // 32
    float* red  = lse + 32;             // 128
    const uint32_t mbar = smem_u32(sm) + 30720u * 4u;

    const int bidx = blockIdx.x;
    const int tid = threadIdx.x;
    const int lane = tid & 31, warp = tid >> 5;

    if (tid == 0) MBAR_INIT(mbar, 1u);
    __syncthreads();
    if (tid == 0) {
        MBAR_EXPECT_TX(mbar, (uint32_t)(NPRED * 2));
        const char* src = (const char*)(pred_g + (size_t)bidx * NPRED);
        uint32_t dst = smem_u32(sm);
#pragma unroll
        for (int p = 0; p < 4; p++)
            BULK_G2S(dst + p * (NPRED / 2), src + (size_t)p * (NPRED / 2),
                     (uint32_t)(NPRED / 2), mbar);
    }

    if (tid < 100) red[tid] = fmaxf(sf[(size_t)bidx * 100 + tid], 0.f);
    __syncthreads();
    if (tid < 32) {
        float s = red[tid] + red[tid + 32] + red[tid + 64] + ((tid < 4) ? red[tid + 96] : 0.f);
#pragma unroll
        for (int o = 16; o; o >>= 1) s += __shfl_xor_sync(~0u, s, o);
        if (tid == 0) red[112] = s;
    }
    __syncthreads();
    float invs = 1.f / fmaxf(red[112], 1e-6f);
    __syncthreads();
    if (tid < 100) red[tid] = red[tid] * invs - 0.01f;
    __syncthreads();
    if (tid < 100) {
        float a = 0.f;
        for (int s = 0; s < 100; s++) a += red[s] * priors[s * 100 + tid];
        sp[tid] = a;
    }
    __syncthreads();

    for (int idx = tid; idx < 3200; idx += 1024) bq[idx] = sp[idx % 100] * 0.1f;

    MBAR_WAIT(mbar, 0);
    __syncthreads();

    for (int it = 0; it < 3; it++) {
        {
            float b0 = bq[warp * 100 + lane];
            float b1 = bq[warp * 100 + 32 + lane];
            float b2 = bq[warp * 100 + 64 + lane];
            float b3 = (lane < 4) ? bq[warp * 100 + 96 + lane] : -1e30f;
            float m = fmaxf(fmaxf(b0, b1), fmaxf(b2, b3));
#pragma unroll
            for (int o = 16; o; o >>= 1) m = fmaxf(m, __shfl_xor_sync(~0u, m, o));
            float e0 = expf(b0 - m), e1 = expf(b1 - m), e2 = expf(b2 - m);
            float e3 = (lane < 4) ? expf(b3 - m) : 0.f;
            float s = e0 + e1 + e2 + e3;
#pragma unroll
            for (int o = 16; o; o >>= 1) s += __shfl_xor_sync(~0u, s, o);
            float is = 1.f / s;
            bq[warp * 100 + lane]      = e0 * is;
            bq[warp * 100 + 32 + lane] = e1 * is;
            bq[warp * 100 + 64 + lane] = e2 * is;
            if (lane < 4) bq[warp * 100 + 96 + lane] = e3 * is;
            if (lane == 0) { mrow[warp] = m; lse[warp] = logf(s); }
        }
        __syncthreads();

        // s[j,o-pair] over 800 half2 items
        if (tid < 800) {
            int j = tid >> 3;
            float s0 = 0.f, s1 = 0.f;
#pragma unroll 8
            for (int n = 0; n < 32; n++) {
                float c = bq[n * 100 + j];
                float2 p = __half22float2(ph2[n * 800 + tid]);
                s0 += c * p.x; s1 += c * p.y;
            }
            int o2 = (tid & 7) * 2;
            vv[j * 16 + o2] = s0;
            vv[j * 16 + o2 + 1] = s1;
        }
        __syncthreads();
        if (tid < 100) {
            float sq = 0.f;
#pragma unroll
            for (int o = 0; o < 16; o++) { float t = vv[tid * 16 + o]; sq += t * t; }
            red[tid] = (sq / (1.f + sq)) * rsqrtf(sq + 1e-8f);
        }
        __syncthreads();
        for (int idx = tid; idx < 1600; idx += 1024) vv[idx] *= red[idx >> 4];
        __syncthreads();

        if (it < 2) {
            float strength = 0.1f - 0.02f * (it + 1);
            for (int idx = tid; idx < 3200; idx += 1024) {
                int n = idx / 100, j = idx - n * 100;
                float c = bq[idx];
                const __half2* pp = ph2 + n * 800 + j * 8;
                float dot = 0.f;
#pragma unroll
                for (int op = 0; op < 8; op++) {
                    float2 p = __half22float2(pp[op]);
                    dot += p.x * vv[j * 16 + op * 2] + p.y * vv[j * 16 + op * 2 + 1];
                }
                bq[idx] = logf(fmaxf(c, 1e-38f)) + mrow[n] + lse[n] + dot + sp[j] * strength;
            }
            __syncthreads();
        }
    }

    if (tid < 100) {
        float nr = 0.f, dt = 0.f;
#pragma unroll
        for (int o = 0; o < 16; o++) {
            float v = vv[tid * 16 + o];
            nr += v * v;
            dt += v * targets[tid * 16 + o];
        }
        out[(size_t)bidx * 100 + tid] = temp_p[0] * dt / fmaxf(sqrtf(nr), 1e-12f);
    }
}

extern "C" void kernel_launch(void* const* d_in, const int* in_sizes, int n_in,
                              void* d_out, int out_size) {
    const float* features = (const float*)d_in[0];
    const float* slot_f   = (const float*)d_in[1];
    const float* W1       = (const float*)d_in[2];
    const float* b1       = (const float*)d_in[3];
    const float* W2       = (const float*)d_in[4];
    const float* b2       = (const float*)d_in[5];
    const float* ln_g     = (const float*)d_in[6];
    const float* ln_b     = (const float*)d_in[7];
    const float* pc_W     = (const float*)d_in[8];
    const float* pc_b     = (const float*)d_in[9];
    const float* pc_g     = (const float*)d_in[10];
    const float* pc_beta  = (const float*)d_in[11];
    const float* dc_W     = (const float*)d_in[12];
    const float* priors   = (const float*)d_in[13];
    const float* targets  = (const float*)d_in[14];
    const float* temp     = (const float*)d_in[15];
    float* out = (float*)d_out;

    float* h1; cudaGetSymbolAddress((void**)&h1, g_h1);
    float* h2; cudaGetSymbolAddress((void**)&h2, g_h2);
    float* pr; cudaGetSymbolAddress((void**)&pr, g_prim);
    __half* pd; cudaGetSymbolAddress((void**)&pd, g_pred);
    char* Ah; cudaGetSymbolAddress((void**)&Ah, g_Ahi);
    char* Al; cudaGetSymbolAddress((void**)&Al, g_Alo);
    char* Wh; cudaGetSymbolAddress((void**)&Wh, g_Whi);
    char* Wl; cudaGetSymbolAddress((void**)&Wl, g_Wlo);

    const int RSMEM = 30720 * 4 + 32;     // 122912 B
    cudaFuncSetAttribute(routing_kernel, cudaFuncAttributeMaxDynamicSharedMemorySize, RSMEM);
    const int GSMEM = 1024 + 3 * STGB;    // 197632 B
    cudaFuncSetAttribute(gemm1_mma, cudaFuncAttributeMaxDynamicSharedMemorySize, GSMEM);

    splitA<<<dim3((KP / 8 + 255) / 256, BATCH), 256>>>(features, Ah, Al);
    splitW<<<dim3(KP / 32, H1DIM / 32), 256>>>(W1, Wh, Wl);
    gemm1_mma<<<dim3(H1DIM / 128, BATCH / 128), 256, GSMEM>>>(Ah, Al, Wh, Wl, b1, h1);
    gemm_bias_relu<<<dim3(256/128, 4096/128), 256>>>(h1, W2, b2, h2, 4096, 256, 512);
    prim_kernel<<<512, 256>>>(h2, ln_g, ln_b, pc_W, pc_b, pc_g, pc_beta, pr);
    pred_kernel<<<BATCH / 32, 256>>>(pr, dc_W, pd);
    routing_kernel<<<4096, 1024, RSMEM>>>(pd, slot_f, priors, targets, temp, out);
}

// round 13
// speedup vs baseline: 1.0675x; 1.0250x over previous
#include <cuda_runtime.h>
#include <cuda_bf16.h>
#include <cuda_fp16.h>
#include <math.h>
#include <stdint.h>

#define BATCH  4096
#define IN_DIM 20000
#define H1DIM  512
#define H2DIM  256
#define NCAPS  32
#define PDIM   8
#define CDIM   16
#define NLAB   100

#define KP     20032            // IN_DIM padded to 313*64
#define NCH    313              // chunks
#define TILEB  16384            // one tile: 128 rows x 128 B (swizzled), contiguous
#define STGB   (4 * TILEB)      // stage: Ah, Al, Wh, Wl
#define NPRED  51200            // 32*100*16 per item

__device__ float g_h1[BATCH * H1DIM];
__device__ float g_h2[BATCH * H2DIM];
__device__ float g_prim[BATCH * NCAPS * PDIM];
__device__ __half g_pred[(size_t)BATCH * NPRED];
// tiled, pre-swizzled bf16 buffers
__device__ __align__(128) char g_Ahi[(size_t)32 * NCH * TILEB];
__device__ __align__(128) char g_Alo[(size_t)32 * NCH * TILEB];
__device__ __align__(128) char g_Whi[(size_t)4 * NCH * TILEB];
__device__ __align__(128) char g_Wlo[(size_t)4 * NCH * TILEB];

// ---------------- helpers ----------------
__device__ __forceinline__ uint32_t smem_u32(const void* p) {
    uint32_t a;
    asm("{ .reg .u64 t; cvta.to.shared.u64 t, %1; cvt.u32.u64 %0, t; }" : "=r"(a) : "l"(p));
    return a;
}
__device__ __forceinline__ uint32_t sw128(uint32_t off) {
    return off ^ ((off >> 3) & 0x70);
}
__device__ __forceinline__ void ldm_x4(uint32_t* r, uint32_t addr) {
    asm volatile("ldmatrix.sync.aligned.m8n8.x4.shared.b16 {%0,%1,%2,%3}, [%4];"
                 : "=r"(r[0]), "=r"(r[1]), "=r"(r[2]), "=r"(r[3]) : "r"(addr));
}
__device__ __forceinline__ void mma_bf16(float* c, const uint32_t* a, const uint32_t* b) {
    asm volatile("mma.sync.aligned.m16n8k16.row.col.f32.bf16.bf16.f32 "
                 "{%0,%1,%2,%3}, {%4,%5,%6,%7}, {%8,%9}, {%0,%1,%2,%3};"
                 : "+f"(c[0]), "+f"(c[1]), "+f"(c[2]), "+f"(c[3])
                 : "r"(a[0]), "r"(a[1]), "r"(a[2]), "r"(a[3]), "r"(b[0]), "r"(b[1]));
}
__device__ __forceinline__ uint32_t pack_bf2(__nv_bfloat16 a, __nv_bfloat16 b) {
    __nv_bfloat162 t; t.x = a; t.y = b;
    return *(uint32_t*)&t;
}
#define MBAR_INIT(a, c) asm volatile("mbarrier.init.shared.b64 [%0], %1;" :: "r"(a), "r"(c) : "memory")
#define MBAR_EXPECT_TX(a, b) asm volatile("mbarrier.arrive.expect_tx.shared.b64 _, [%0], %1;" :: "r"(a), "r"(b) : "memory")
#define BULK_G2S(dst, src, sz, mbar) \
    asm volatile("cp.async.bulk.shared::cluster.global.mbarrier::complete_tx::bytes [%0], [%1], %2, [%3];" \
                 :: "r"(dst), "l"(src), "r"(sz), "r"(mbar) : "memory")

#define MBAR_WAIT(mbar_smem_addr, phase_parity) do { \
    uint32_t _mbar = (uint32_t)(mbar_smem_addr); \
    uint32_t _parity = (uint32_t)(phase_parity); \
    uint32_t _done; \
    asm volatile( \
        "{\n\t.reg .pred p;\n\t" \
        "mbarrier.try_wait.parity.acquire.cta.shared::cta.b64 p, [%1], %2;\n\t" \
        "selp.b32 %0, 1, 0, p;\n\t}" \
        : "=r"(_done) : "r"(_mbar), "r"(_parity) : "memory"); \
    if (!_done) { \
        asm volatile( \
            "{\n\t.reg .pred P1;\n\t" \
            "WAIT_LOOP_%=:\n\t" \
            "mbarrier.try_wait.parity.acquire.cta.shared::cta.b64 P1, [%0], %1, 0x989680;\n\t" \
            "@P1 bra.uni WAIT_DONE_%=;\n\t" \
            "bra.uni WAIT_LOOP_%=;\n\t" \
            "WAIT_DONE_%=:\n\t}" \
            :: "r"(_mbar), "r"(_parity) : "memory"); \
    } \
} while(0)

// ---------------- prep: split features -> tiled swizzled bf16 hi/lo --------
__global__ void __launch_bounds__(256)
splitA(const float* __restrict__ F, char* __restrict__ Ah, char* __restrict__ Al) {
    int m = blockIdx.y;
    int u = blockIdx.x * 256 + threadIdx.x;
    if (u >= KP / 8) return;
    int k0 = u * 8;
    float v[8];
    if (k0 < IN_DIM) {
        const float4* fp = (const float4*)(F + (size_t)m * IN_DIM + k0);
        float4 f0 = fp[0], f1 = fp[1];
        v[0]=f0.x; v[1]=f0.y; v[2]=f0.z; v[3]=f0.w;
        v[4]=f1.x; v[5]=f1.y; v[6]=f1.z; v[7]=f1.w;
    } else {
#pragma unroll
        for (int j = 0; j < 8; j++) v[j] = 0.f;
    }
    uint32_t hi[4], lo[4];
#pragma unroll
    for (int j = 0; j < 4; j++) {
        float a = v[2*j], b = v[2*j+1];
        __nv_bfloat16 ha = __float2bfloat16(a), hb = __float2bfloat16(b);
        float la = a - __bfloat162float(ha), lb = b - __bfloat162float(hb);
        hi[j] = pack_bf2(ha, hb);
        lo[j] = pack_bf2(__float2bfloat16(la), __float2bfloat16(lb));
    }
    int mt = m >> 7, row = m & 127, ch = u >> 3, u8 = u & 7;
    uint32_t off = sw128((uint32_t)(row * 128 + u8 * 16));
    size_t addr = ((size_t)mt * NCH + ch) * TILEB + off;
    *(uint4*)(Ah + addr) = make_uint4(hi[0], hi[1], hi[2], hi[3]);
    *(uint4*)(Al + addr) = make_uint4(lo[0], lo[1], lo[2], lo[3]);
}

// ---------------- prep: transpose+split W1 [K,N] -> tiled swizzled ---------
__global__ void __launch_bounds__(256)
splitW(const float* __restrict__ W1, char* __restrict__ Wh, char* __restrict__ Wl) {
    __shared__ float ts[32][33];
    int k0 = blockIdx.x * 32, n0 = blockIdx.y * 32;
    int tx = threadIdx.x & 31, ty = threadIdx.x >> 5;
#pragma unroll
    for (int r = 0; r < 32; r += 8) {
        int k = k0 + ty + r;
        ts[ty + r][tx] = (k < IN_DIM) ? W1[(size_t)k * H1DIM + n0 + tx] : 0.f;
    }
    __syncthreads();
#pragma unroll
    for (int r = 0; r < 32; r += 8) {
        int n = n0 + ty + r;
        int k = k0 + tx;
        float x = ts[tx][ty + r];
        __nv_bfloat16 h = __float2bfloat16(x);
        float lo = x - __bfloat162float(h);
        int nt = n >> 7, row = n & 127, ch = k >> 6, kk = k & 63;
        uint32_t off = sw128((uint32_t)(row * 128 + kk * 2));
        size_t addr = ((size_t)nt * NCH + ch) * TILEB + off;
        *(__nv_bfloat16*)(Wh + addr) = h;
        *(__nv_bfloat16*)(Wl + addr) = __float2bfloat16(lo);
    }
}

// ---------------- GEMM1: 3-stage bulk-TMA + mma.sync bf16 (split hi/lo) ----
__global__ void __launch_bounds__(256)
gemm1_mma(const char* __restrict__ Ath, const char* __restrict__ Atl,
          const char* __restrict__ Wth, const char* __restrict__ Wtl,
          const float* __restrict__ bias, float* __restrict__ C) {
    extern __shared__ __align__(1024) char smem[];
    const uint32_t sb = smem_u32(smem);
    const uint32_t mb0 = sb, mb1 = sb + 8, mb2 = sb + 16;
    const uint32_t stage0 = sb + 1024;
    const int tid = threadIdx.x;
    const int lane = tid & 31, wid = tid >> 5;
    const int wm = wid & 3, wn = wid >> 2;
    const int m0 = blockIdx.y * 128, n0 = blockIdx.x * 128;

    const char* srcs[4] = {
        Ath + (size_t)blockIdx.y * NCH * TILEB,
        Atl + (size_t)blockIdx.y * NCH * TILEB,
        Wth + (size_t)blockIdx.x * NCH * TILEB,
        Wtl + (size_t)blockIdx.x * NCH * TILEB
    };

    if (tid == 0) { MBAR_INIT(mb0, 1u); MBAR_INIT(mb1, 1u); MBAR_INIT(mb2, 1u); }
    __syncthreads();

    const int aq = lane >> 3;
    const uint32_t a_row = (uint32_t)((aq & 1) * 8 + (lane & 7));
    const uint32_t a_colb = (uint32_t)((aq >> 1) * 16);
    const uint32_t b_row = (uint32_t)(((aq & 2) ? 8 : 0) + (lane & 7));
    const uint32_t b_colb = (uint32_t)((aq & 1) * 16);

    float acc[2][8][4];
#pragma unroll
    for (int mt = 0; mt < 2; mt++)
#pragma unroll
        for (int nt = 0; nt < 8; nt++)
#pragma unroll
            for (int e = 0; e < 4; e++) acc[mt][nt][e] = 0.f;

    if (tid == 0) {
#pragma unroll
        for (int c = 0; c < 2; c++) {
            uint32_t mbc = sb + 8u * c;
            MBAR_EXPECT_TX(mbc, (uint32_t)STGB);
#pragma unroll
            for (int p = 0; p < 4; p++)
                BULK_G2S(stage0 + c * STGB + p * TILEB, srcs[p] + (size_t)c * TILEB,
                         (uint32_t)TILEB, mbc);
        }
    }

    int s = 0, ph0 = 0, ph1 = 0, ph2v = 0;
    for (int t = 0; t < NCH; ++t) {
        if (t + 2 < NCH && tid == 0) {
            int s2 = s + 2; if (s2 >= 3) s2 -= 3;
            uint32_t mbn = sb + 8u * s2;
            uint32_t stn = stage0 + (uint32_t)(s2 * STGB);
            MBAR_EXPECT_TX(mbn, (uint32_t)STGB);
#pragma unroll
            for (int p = 0; p < 4; p++)
                BULK_G2S(stn + p * TILEB, srcs[p] + (size_t)(t + 2) * TILEB,
                         (uint32_t)TILEB, mbn);
        }
        if (s == 0)      { MBAR_WAIT(mb0, ph0); ph0 ^= 1; }
        else if (s == 1) { MBAR_WAIT(mb1, ph1); ph1 ^= 1; }
        else             { MBAR_WAIT(mb2, ph2v); ph2v ^= 1; }

        const uint32_t st = stage0 + (uint32_t)(s * STGB);
        const uint32_t aRow = (uint32_t)(wm * 32) + a_row;
        const uint32_t bRow = (uint32_t)(wn * 64) + b_row;

#pragma unroll
        for (int ks = 0; ks < 4; ++ks) {
            const uint32_t kb = (uint32_t)(ks * 32);
            uint32_t ah[2][4], al[2][4];
#pragma unroll
            for (int mt = 0; mt < 2; mt++) {
                uint32_t off = sw128((aRow + mt * 16) * 128 + kb + a_colb);
                ldm_x4(ah[mt], st + 0 * TILEB + off);
                ldm_x4(al[mt], st + 1 * TILEB + off);
            }
            uint32_t bh[8][2], bl[8][2];
#pragma unroll
            for (int np = 0; np < 4; np++) {
                uint32_t off = sw128((bRow + np * 16) * 128 + kb + b_colb);
                uint32_t rh[4], rl[4];
                ldm_x4(rh, st + 2 * TILEB + off);
                ldm_x4(rl, st + 3 * TILEB + off);
                bh[np * 2][0] = rh[0]; bh[np * 2][1] = rh[1];
                bh[np * 2 + 1][0] = rh[2]; bh[np * 2 + 1][1] = rh[3];
                bl[np * 2][0] = rl[0]; bl[np * 2][1] = rl[1];
                bl[np * 2 + 1][0] = rl[2]; bl[np * 2 + 1][1] = rl[3];
            }
#pragma unroll
            for (int mt = 0; mt < 2; mt++)
#pragma unroll
                for (int nt = 0; nt < 8; nt++) {
                    mma_bf16(acc[mt][nt], ah[mt], bh[nt]);
                    mma_bf16(acc[mt][nt], al[mt], bh[nt]);
                    mma_bf16(acc[mt][nt], ah[mt], bl[nt]);
                }
        }
        __syncthreads();
        s = (s + 1 == 3) ? 0 : s + 1;
    }

    const int l4 = lane >> 2, l2 = (lane & 3) * 2;
    const int ncol0 = n0 + wn * 64;
#pragma unroll
    for (int mt = 0; mt < 2; mt++) {
        int m = m0 + wm * 32 + mt * 16 + l4;
        float* r0 = C + (size_t)m * H1DIM + ncol0;
        float* r1 = r0 + (size_t)8 * H1DIM;
#pragma unroll
        for (int nt = 0; nt < 8; nt++) {
            int col = nt * 8 + l2;
            float b0 = bias[ncol0 + col], b1 = bias[ncol0 + col + 1];
            float v0 = fmaxf(acc[mt][nt][0] + b0, 0.f);
            float v1 = fmaxf(acc[mt][nt][1] + b1, 0.f);
            float v2 = fmaxf(acc[mt][nt][2] + b0, 0.f);
            float v3 = fmaxf(acc[mt][nt][3] + b1, 0.f);
            *(float2*)&r0[col] = make_float2(v0, v1);
            *(float2*)&r1[col] = make_float2(v2, v3);
        }
    }
}

// -------- f32x2 packed FMA helpers (GEMM2) --------
__device__ __forceinline__ unsigned long long dup2(float x) {
    unsigned long long r; asm("mov.b64 %0, {%1, %1};" : "=l"(r) : "f"(x)); return r;
}
__device__ __forceinline__ void fma2(unsigned long long& d, unsigned long long a, unsigned long long b) {
    asm("fma.rn.f32x2 %0, %1, %2, %0;" : "+l"(d) : "l"(a), "l"(b));
}
__device__ __forceinline__ void unp2(unsigned long long v, float& lo, float& hi) {
    asm("mov.b64 {%0, %1}, %2;" : "=f"(lo), "=f"(hi) : "l"(v));
}

// -------- GEMM2 (fp32): BM=64 for 128-CTA occupancy, C = relu(A@B + b) -----
__global__ void __launch_bounds__(256)
gemm2_64(const float* __restrict__ A, const float* __restrict__ B,
         const float* __restrict__ bias, float* __restrict__ C,
         int M, int N, int K) {
    const int BKf = 16;
    __shared__ __align__(16) float As[2][16][72];
    __shared__ __align__(16) float Bs[2][16][128];

    const int tid = threadIdx.x;
    const int tx = tid & 15, ty = tid >> 4;       // tx: 8 cols, ty: 4 rows
    const int m0 = blockIdx.y * 64, n0 = blockIdx.x * 128;
    const int ar0 = tid >> 2, ak0 = (tid & 3) * 4;
    const int br0 = tid >> 5, bc0 = (tid & 31) * 4;

    const float* Aptr = A + (size_t)(m0 + ar0) * K + ak0;
    const float* Bptr = B + (size_t)br0 * N + n0 + bc0;

    unsigned long long acc[4][4];
#pragma unroll
    for (int i = 0; i < 4; i++)
#pragma unroll
        for (int j = 0; j < 4; j++) acc[i][j] = 0ull;

    float4 a0f = *(const float4*)Aptr;
    float4 b0f = *(const float4*)Bptr;
    float4 b1f = *(const float4*)(Bptr + 8 * N);

    As[0][ak0+0][ar0] = a0f.x; As[0][ak0+1][ar0] = a0f.y;
    As[0][ak0+2][ar0] = a0f.z; As[0][ak0+3][ar0] = a0f.w;
    *(float4*)&Bs[0][br0][bc0] = b0f;
    *(float4*)&Bs[0][br0+8][bc0] = b1f;
    __syncthreads();

    const int nT = K / BKf;
    int buf = 0;
    for (int t = 0; t < nT; ++t) {
        if (t + 1 < nT) {
            a0f = *(const float4*)(Aptr + (t + 1) * BKf);
            const float* Bp = Bptr + (size_t)(t + 1) * BKf * N;
            b0f = *(const float4*)Bp;
            b1f = *(const float4*)(Bp + 8 * N);
        }
#pragma unroll
        for (int k = 0; k < BKf; ++k) {
            float4 av = *(const float4*)&As[buf][k][ty * 4];
            ulonglong2 bA = *(const ulonglong2*)&Bs[buf][k][tx * 8];
            ulonglong2 bB = *(const ulonglong2*)&Bs[buf][k][tx * 8 + 4];
            float avf[4] = {av.x, av.y, av.z, av.w};
#pragma unroll
            for (int i = 0; i < 4; i++) {
                unsigned long long ad = dup2(avf[i]);
                fma2(acc[i][0], ad, bA.x);
                fma2(acc[i][1], ad, bA.y);
                fma2(acc[i][2], ad, bB.x);
                fma2(acc[i][3], ad, bB.y);
            }
        }
        if (t + 1 < nT) {
            int nb = buf ^ 1;
            As[nb][ak0+0][ar0] = a0f.x; As[nb][ak0+1][ar0] = a0f.y;
            As[nb][ak0+2][ar0] = a0f.z; As[nb][ak0+3][ar0] = a0f.w;
            *(float4*)&Bs[nb][br0][bc0] = b0f;
            *(float4*)&Bs[nb][br0+8][bc0] = b1f;
        }
        __syncthreads();
        buf ^= 1;
    }

    float bb[8];
#pragma unroll
    for (int c = 0; c < 8; c++) bb[c] = bias[n0 + tx * 8 + c];
#pragma unroll
    for (int i = 0; i < 4; i++) {
        float* Crow = C + (size_t)(m0 + ty * 4 + i) * N + n0 + tx * 8;
#pragma unroll
        for (int j = 0; j < 4; j++) {
            float lo, hi; unp2(acc[i][j], lo, hi);
            lo = fmaxf(lo + bb[2*j], 0.f);
            hi = fmaxf(hi + bb[2*j+1], 0.f);
            *(float2*)&Crow[2*j] = make_float2(lo, hi);
        }
    }
}

// -------- primary caps: fused row-LN + einsum + bias + per-capsule LN ------
__global__ void __launch_bounds__(256)
prim_kernel(const float* __restrict__ h2, const float* __restrict__ lng,
            const float* __restrict__ lnb, const float* __restrict__ pcW,
            const float* __restrict__ pcB, const float* __restrict__ pcG,
            const float* __restrict__ pcBeta, float* __restrict__ prim) {
    __shared__ float hs[8 * 256];
    int tid = threadIdx.x;
    int row0 = blockIdx.x * 8;
    for (int i = tid; i < 2048; i += 256) hs[i] = h2[(size_t)row0 * 256 + i];
    __syncthreads();

    {
        int warp = tid >> 5, lane = tid & 31;
        float* xr = hs + warp * 256;
        float x[8];
#pragma unroll
        for (int e = 0; e < 8; e++) x[e] = xr[lane + 32 * e];
        float s = 0.f;
#pragma unroll
        for (int e = 0; e < 8; e++) s += x[e];
#pragma unroll
        for (int o = 16; o; o >>= 1) s += __shfl_xor_sync(~0u, s, o);
        float mu = s * (1.f / 256.f);
        float vs = 0.f;
#pragma unroll
        for (int e = 0; e < 8; e++) { float d = x[e] - mu; vs += d * d; }
#pragma unroll
        for (int o = 16; o; o >>= 1) vs += __shfl_xor_sync(~0u, vs, o);
        float inv = rsqrtf(vs * (1.f / 256.f) + 1e-5f);
#pragma unroll
        for (int e = 0; e < 8; e++) {
            int c = lane + 32 * e;
            xr[c] = (x[e] - mu) * inv * lng[c] + lnb[c];
        }
    }
    __syncthreads();

    int n = tid >> 3;
    float acc[8] = {0,0,0,0,0,0,0,0};
    const float* w = pcW + n * 2048 + (tid & 7);
    for (int c = 0; c < 256; c += 4) {
        float w0 = w[(c+0)*8], w1 = w[(c+1)*8], w2 = w[(c+2)*8], w3 = w[(c+3)*8];
#pragma unroll
        for (int r = 0; r < 8; r++)
            acc[r] += hs[r*256+c]*w0 + hs[r*256+c+1]*w1 + hs[r*256+c+2]*w2 + hs[r*256+c+3]*w3;
    }
    float bn = pcB[tid], gg = pcG[tid], bt = pcBeta[tid];
#pragma unroll
    for (int r = 0; r < 8; r++) {
        float x = acc[r] + bn;
        float s = x;
        s += __shfl_xor_sync(~0u, s, 1); s += __shfl_xor_sync(~0u, s, 2); s += __shfl_xor_sync(~0u, s, 4);
        float mu = s * 0.125f;
        float dv = x - mu;
        float v = dv * dv;
        v += __shfl_xor_sync(~0u, v, 1); v += __shfl_xor_sync(~0u, v, 2); v += __shfl_xor_sync(~0u, v, 4);
        float inv = rsqrtf(v * 0.125f + 1e-5f);
        prim[(size_t)(row0 + r) * 256 + tid] = dv * inv * gg + bt;
    }
}

// -------- predictions GEMM: 32 items/CTA, e8-units, STG.128 fp16 out -------
__global__ void __launch_bounds__(256)
pred_kernel(const float* __restrict__ prim, const float* __restrict__ dcW,
            __half* __restrict__ pred) {
    __shared__ float ps[32 * 256];
    const int tid = threadIdx.x;
    const int m0 = blockIdx.x * 32;
    for (int i = tid; i < 32 * 256 / 4; i += 256)
        ((float4*)ps)[i] = ((const float4*)(prim + (size_t)m0 * 256))[i];
    __syncthreads();

    for (int eg = 0; eg < 25; eg++) {
        int e8 = tid + eg * 256;          // 8-elem unit, 0..6399
        int e = e8 * 8;
        int n = e / 1600;                  // same n for all 8 (1600 % 8 == 0)
        float4 w[16];
        const float4* wp = (const float4*)(dcW + (size_t)e * 8);
#pragma unroll
        for (int q = 0; q < 16; q++) w[q] = wp[q];
#pragma unroll 2
        for (int i = 0; i < 32; i++) {
            const float* p = ps + i * 256 + n * 8;
            float4 pa = *(const float4*)p;
            float4 pb = *(const float4*)(p + 4);
            float r[8];
#pragma unroll
            for (int q = 0; q < 8; q++) {
                r[q] = w[2*q].x*pa.x + w[2*q].y*pa.y + w[2*q].z*pa.z + w[2*q].w*pa.w
                     + w[2*q+1].x*pb.x + w[2*q+1].y*pb.y + w[2*q+1].z*pb.z + w[2*q+1].w*pb.w;
            }
            __half2 h0 = __floats2half2_rn(r[0], r[1]);
            __half2 h1 = __floats2half2_rn(r[2], r[3]);
            __half2 h2v = __floats2half2_rn(r[4], r[5]);
            __half2 h3 = __floats2half2_rn(r[6], r[7]);
            uint4 u;
            u.x = *(uint32_t*)&h0; u.y = *(uint32_t*)&h1;
            u.z = *(uint32_t*)&h2v; u.w = *(uint32_t*)&h3;
            *(uint4*)(pred + (size_t)(m0 + i) * NPRED + e) = u;
        }
    }
}

// -------- fused routing + logits; fp16 pred via bulk copy ------------------
__global__ void __launch_bounds__(1024)
routing_kernel(const __half* __restrict__ pred_g,
               const float* __restrict__ sf, const float* __restrict__ priors,
               const float* __restrict__ targets, const float* __restrict__ temp_p,
               float* __restrict__ out) {
    extern __shared__ float sm[];
    __half2* ph2 = (__half2*)sm;        // 25600 half2 = 25600 float slots
    float* bq   = sm + 25600;           // 3200
    float* vv   = bq + 3200;            // 1600
    float* sp   = vv + 1600;            // 128
    float* mrow = sp + 128;             // 32
    float* lse  = mrow + 32;            // 32
    float* red  = lse + 32;             // 128
    const uint32_t mbar = smem_u32(sm) + 30720u * 4u;

    const int bidx = blockIdx.x;
    const int tid = threadIdx.x;
    const int lane = tid & 31, warp = tid >> 5;

    if (tid == 0) MBAR_INIT(mbar, 1u);
    __syncthreads();
    if (tid == 0) {
        MBAR_EXPECT_TX(mbar, (uint32_t)(NPRED * 2));
        const char* src = (const char*)(pred_g + (size_t)bidx * NPRED);
        uint32_t dst = smem_u32(sm);
#pragma unroll
        for (int p = 0; p < 4; p++)
            BULK_G2S(dst + p * (NPRED / 2), src + (size_t)p * (NPRED / 2),
                     (uint32_t)(NPRED / 2), mbar);
    }

    if (tid < 100) red[tid] = fmaxf(sf[(size_t)bidx * 100 + tid], 0.f);
    __syncthreads();
    if (tid < 32) {
        float s = red[tid] + red[tid + 32] + red[tid + 64] + ((tid < 4) ? red[tid + 96] : 0.f);
#pragma unroll
        for (int o = 16; o; o >>= 1) s += __shfl_xor_sync(~0u, s, o);
        if (tid == 0) red[112] = s;
    }
    __syncthreads();
    float invs = 1.f / fmaxf(red[112], 1e-6f);
    __syncthreads();
    if (tid < 100) red[tid] = red[tid] * invs - 0.01f;
    __syncthreads();
    if (tid < 100) {
        float a = 0.f;
        for (int s = 0; s < 100; s++) a += red[s] * priors[s * 100 + tid];
        sp[tid] = a;
    }
    __syncthreads();

    for (int idx = tid; idx < 3200; idx += 1024) bq[idx] = sp[idx % 100] * 0.1f;

    MBAR_WAIT(mbar, 0);
    __syncthreads();

    for (int it = 0; it < 3; it++) {
        {
            float b0 = bq[warp * 100 + lane];
            float b1 = bq[warp * 100 + 32 + lane];
            float b2 = bq[warp * 100 + 64 + lane];
            float b3 = (lane < 4) ? bq[warp * 100 + 96 + lane] : -1e30f;
            float m = fmaxf(fmaxf(b0, b1), fmaxf(b2, b3));
#pragma unroll
            for (int o = 16; o; o >>= 1) m = fmaxf(m, __shfl_xor_sync(~0u, m, o));
            float e0 = __expf(b0 - m), e1 = __expf(b1 - m), e2 = __expf(b2 - m);
            float e3 = (lane < 4) ? __expf(b3 - m) : 0.f;
            float s = e0 + e1 + e2 + e3;
#pragma unroll
            for (int o = 16; o; o >>= 1) s += __shfl_xor_sync(~0u, s, o);
            float is = 1.f / s;
            bq[warp * 100 + lane]      = e0 * is;
            bq[warp * 100 + 32 + lane] = e1 * is;
            bq[warp * 100 + 64 + lane] = e2 * is;
            if (lane < 4) bq[warp * 100 + 96 + lane] = e3 * is;
            if (lane == 0) { mrow[warp] = m; lse[warp] = __logf(s); }
        }
        __syncthreads();

        if (tid < 800) {
            int j = tid >> 3;
            float s0 = 0.f, s1 = 0.f;
#pragma unroll 8
            for (int n = 0; n < 32; n++) {
                float c = bq[n * 100 + j];
                float2 p = __half22float2(ph2[n * 800 + tid]);
                s0 += c * p.x; s1 += c * p.y;
            }
            int o2 = (tid & 7) * 2;
            vv[j * 16 + o2] = s0;
            vv[j * 16 + o2 + 1] = s1;
        }
        __syncthreads();
        if (tid < 100) {
            float sq = 0.f;
#pragma unroll
            for (int o = 0; o < 16; o++) { float t = vv[tid * 16 + o]; sq += t * t; }
            red[tid] = (sq / (1.f + sq)) * rsqrtf(sq + 1e-8f);
        }
        __syncthreads();
        for (int idx = tid; idx < 1600; idx += 1024) vv[idx] *= red[idx >> 4];
        __syncthreads();

        if (it < 2) {
            float strength = 0.1f - 0.02f * (it + 1);
            for (int idx = tid; idx < 3200; idx += 1024) {
                int n = idx / 100, j = idx - n * 100;
                float c = bq[idx];
                const __half2* pp = ph2 + n * 800 + j * 8;
                float dot = 0.f;
#pragma unroll
                for (int op = 0; op < 8; op++) {
                    float2 p = __half22float2(pp[op]);
                    dot += p.x * vv[j * 16 + op * 2] + p.y * vv[j * 16 + op * 2 + 1];
                }
                bq[idx] = __logf(fmaxf(c, 1e-38f)) + mrow[n] + lse[n] + dot + sp[j] * strength;
            }
            __syncthreads();
        }
    }

    if (tid < 100) {
        float nr = 0.f, dt = 0.f;
#pragma unroll
        for (int o = 0; o < 16; o++) {
            float v = vv[tid * 16 + o];
            nr += v * v;
            dt += v * targets[tid * 16 + o];
        }
        out[(size_t)bidx * 100 + tid] = temp_p[0] * dt / fmaxf(sqrtf(nr), 1e-12f);
    }
}

extern "C" void kernel_launch(void* const* d_in, const int* in_sizes, int n_in,
                              void* d_out, int out_size) {
    const float* features = (const float*)d_in[0];
    const float* slot_f   = (const float*)d_in[1];
    const float* W1       = (const float*)d_in[2];
    const float* b1       = (const float*)d_in[3];
    const float* W2       = (const float*)d_in[4];
    const float* b2       = (const float*)d_in[5];
    const float* ln_g     = (const float*)d_in[6];
    const float* ln_b     = (const float*)d_in[7];
    const float* pc_W     = (const float*)d_in[8];
    const float* pc_b     = (const float*)d_in[9];
    const float* pc_g     = (const float*)d_in[10];
    const float* pc_beta  = (const float*)d_in[11];
    const float* dc_W     = (const float*)d_in[12];
    const float* priors   = (const float*)d_in[13];
    const float* targets  = (const float*)d_in[14];
    const float* temp     = (const float*)d_in[15];
    float* out = (float*)d_out;

    float* h1; cudaGetSymbolAddress((void**)&h1, g_h1);
    float* h2; cudaGetSymbolAddress((void**)&h2, g_h2);
    float* pr; cudaGetSymbolAddress((void**)&pr, g_prim);
    __half* pd; cudaGetSymbolAddress((void**)&pd, g_pred);
    char* Ah; cudaGetSymbolAddress((void**)&Ah, g_Ahi);
    char* Al; cudaGetSymbolAddress((void**)&Al, g_Alo);
    char* Wh; cudaGetSymbolAddress((void**)&Wh, g_Whi);
    char* Wl; cudaGetSymbolAddress((void**)&Wl, g_Wlo);

    const int RSMEM = 30720 * 4 + 32;     // 122912 B
    cudaFuncSetAttribute(routing_kernel, cudaFuncAttributeMaxDynamicSharedMemorySize, RSMEM);
    const int GSMEM = 1024 + 3 * STGB;    // 197632 B
    cudaFuncSetAttribute(gemm1_mma, cudaFuncAttributeMaxDynamicSharedMemorySize, GSMEM);

    splitA<<<dim3((KP / 8 + 255) / 256, BATCH), 256>>>(features, Ah, Al);
    splitW<<<dim3(KP / 32, H1DIM / 32), 256>>>(W1, Wh, Wl);
    gemm1_mma<<<dim3(H1DIM / 128, BATCH / 128), 256, GSMEM>>>(Ah, Al, Wh, Wl, b1, h1);
    gemm2_64<<<dim3(256 / 128, 4096 / 64), 256>>>(h1, W2, b2, h2, 4096, 256, 512);
    prim_kernel<<<512, 256>>>(h2, ln_g, ln_b, pc_W, pc_b, pc_g, pc_beta, pr);
    pred_kernel<<<BATCH / 32, 256>>>(pr, dc_W, pd);
    routing_kernel<<<4096, 1024, RSMEM>>>(pd, slot_f, priors, targets, temp, out);
}

// round 14
// speedup vs baseline: 1.2331x; 1.1551x over previous
#include <cuda_runtime.h>
#include <cuda_fp16.h>
#include <math.h>
#include <stdint.h>

#define BATCH  4096
#define IN_DIM 20000
#define H1DIM  512
#define H2DIM  256
#define NCAPS  32
#define PDIM   8
#define CDIM   16
#define NLAB   100

#define KP     20032            // IN_DIM padded to 313*64
#define NCH    313              // chunks
#define TILEB  16384            // one tile: 128 rows x 128 B (swizzled), contiguous
#define STGB   (3 * TILEB)      // stage: Ah, Al, Wh
#define NPRED  51200            // 32*100*16 per item

__device__ float g_h1[BATCH * H1DIM];
__device__ float g_h2[BATCH * H2DIM];
__device__ float g_prim[BATCH * NCAPS * PDIM];
__device__ __half g_pred[(size_t)BATCH * NPRED];
// tiled, pre-swizzled fp16 buffers
__device__ __align__(128) char g_Ahi[(size_t)32 * NCH * TILEB];
__device__ __align__(128) char g_Alo[(size_t)32 * NCH * TILEB];
__device__ __align__(128) char g_Whi[(size_t)4 * NCH * TILEB];

// ---------------- helpers ----------------
__device__ __forceinline__ uint32_t smem_u32(const void* p) {
    uint32_t a;
    asm("{ .reg .u64 t; cvta.to.shared.u64 t, %1; cvt.u32.u64 %0, t; }" : "=r"(a) : "l"(p));
    return a;
}
__device__ __forceinline__ uint32_t sw128(uint32_t off) {
    return off ^ ((off >> 3) & 0x70);
}
__device__ __forceinline__ void ldm_x4(uint32_t* r, uint32_t addr) {
    asm volatile("ldmatrix.sync.aligned.m8n8.x4.shared.b16 {%0,%1,%2,%3}, [%4];"
                 : "=r"(r[0]), "=r"(r[1]), "=r"(r[2]), "=r"(r[3]) : "r"(addr));
}
__device__ __forceinline__ void mma_f16(float* c, const uint32_t* a, const uint32_t* b) {
    asm volatile("mma.sync.aligned.m16n8k16.row.col.f32.f16.f16.f32 "
                 "{%0,%1,%2,%3}, {%4,%5,%6,%7}, {%8,%9}, {%0,%1,%2,%3};"
                 : "+f"(c[0]), "+f"(c[1]), "+f"(c[2]), "+f"(c[3])
                 : "r"(a[0]), "r"(a[1]), "r"(a[2]), "r"(a[3]), "r"(b[0]), "r"(b[1]));
}
__device__ __forceinline__ uint32_t pack_h2(__half a, __half b) {
    __half2 t; t.x = a; t.y = b;
    return *(uint32_t*)&t;
}
#define MBAR_INIT(a, c) asm volatile("mbarrier.init.shared.b64 [%0], %1;" :: "r"(a), "r"(c) : "memory")
#define MBAR_EXPECT_TX(a, b) asm volatile("mbarrier.arrive.expect_tx.shared.b64 _, [%0], %1;" :: "r"(a), "r"(b) : "memory")
#define BULK_G2S(dst, src, sz, mbar) \
    asm volatile("cp.async.bulk.shared::cluster.global.mbarrier::complete_tx::bytes [%0], [%1], %2, [%3];" \
                 :: "r"(dst), "l"(src), "r"(sz), "r"(mbar) : "memory")

#define MBAR_WAIT(mbar_smem_addr, phase_parity) do { \
    uint32_t _mbar = (uint32_t)(mbar_smem_addr); \
    uint32_t _parity = (uint32_t)(phase_parity); \
    uint32_t _done; \
    asm volatile( \
        "{\n\t.reg .pred p;\n\t" \
        "mbarrier.try_wait.parity.acquire.cta.shared::cta.b64 p, [%1], %2;\n\t" \
        "selp.b32 %0, 1, 0, p;\n\t}" \
        : "=r"(_done) : "r"(_mbar), "r"(_parity) : "memory"); \
    if (!_done) { \
        asm volatile( \
            "{\n\t.reg .pred P1;\n\t" \
            "WAIT_LOOP_%=:\n\t" \
            "mbarrier.try_wait.parity.acquire.cta.shared::cta.b64 P1, [%0], %1, 0x989680;\n\t" \
            "@P1 bra.uni WAIT_DONE_%=;\n\t" \
            "bra.uni WAIT_LOOP_%=;\n\t" \
            "WAIT_DONE_%=:\n\t}" \
            :: "r"(_mbar), "r"(_parity) : "memory"); \
    } \
} while(0)

// ---------------- prep: split features -> tiled swizzled fp16 hi/lo --------
__global__ void __launch_bounds__(256)
splitA(const float* __restrict__ F, char* __restrict__ Ah, char* __restrict__ Al) {
    int m = blockIdx.y;
    int u = blockIdx.x * 256 + threadIdx.x;
    if (u >= KP / 8) return;
    int k0 = u * 8;
    float v[8];
    if (k0 < IN_DIM) {
        const float4* fp = (const float4*)(F + (size_t)m * IN_DIM + k0);
        float4 f0 = fp[0], f1 = fp[1];
        v[0]=f0.x; v[1]=f0.y; v[2]=f0.z; v[3]=f0.w;
        v[4]=f1.x; v[5]=f1.y; v[6]=f1.z; v[7]=f1.w;
    } else {
#pragma unroll
        for (int j = 0; j < 8; j++) v[j] = 0.f;
    }
    uint32_t hi[4], lo[4];
#pragma unroll
    for (int j = 0; j < 4; j++) {
        float a = v[2*j], b = v[2*j+1];
        __half ha = __float2half_rn(a), hb = __float2half_rn(b);
        float la = a - __half2float(ha), lb = b - __half2float(hb);
        hi[j] = pack_h2(ha, hb);
        lo[j] = pack_h2(__float2half_rn(la), __float2half_rn(lb));
    }
    int mt = m >> 7, row = m & 127, ch = u >> 3, u8 = u & 7;
    uint32_t off = sw128((uint32_t)(row * 128 + u8 * 16));
    size_t addr = ((size_t)mt * NCH + ch) * TILEB + off;
    *(uint4*)(Ah + addr) = make_uint4(hi[0], hi[1], hi[2], hi[3]);
    *(uint4*)(Al + addr) = make_uint4(lo[0], lo[1], lo[2], lo[3]);
}

// ---------------- prep: transpose W1 [K,N] -> tiled swizzled fp16 ----------
__global__ void __launch_bounds__(256)
splitW(const float* __restrict__ W1, char* __restrict__ Wh) {
    __shared__ float ts[32][33];
    int k0 = blockIdx.x * 32, n0 = blockIdx.y * 32;
    int tx = threadIdx.x & 31, ty = threadIdx.x >> 5;
#pragma unroll
    for (int r = 0; r < 32; r += 8) {
        int k = k0 + ty + r;
        ts[ty + r][tx] = (k < IN_DIM) ? W1[(size_t)k * H1DIM + n0 + tx] : 0.f;
    }
    __syncthreads();
#pragma unroll
    for (int r = 0; r < 32; r += 8) {
        int n = n0 + ty + r;
        int k = k0 + tx;
        float x = ts[tx][ty + r];
        int nt = n >> 7, row = n & 127, ch = k >> 6, kk = k & 63;
        uint32_t off = sw128((uint32_t)(row * 128 + kk * 2));
        size_t addr = ((size_t)nt * NCH + ch) * TILEB + off;
        *(__half*)(Wh + addr) = __float2half_rn(x);
    }
}

// ---------------- GEMM1: 3-stage bulk-TMA + mma.sync fp16 (A hi/lo, W hi) --
__global__ void __launch_bounds__(256)
gemm1_mma(const char* __restrict__ Ath, const char* __restrict__ Atl,
          const char* __restrict__ Wth,
          const float* __restrict__ bias, float* __restrict__ C) {
    extern __shared__ __align__(1024) char smem[];
    const uint32_t sb = smem_u32(smem);
    const uint32_t mb0 = sb, mb1 = sb + 8, mb2 = sb + 16;
    const uint32_t stage0 = sb + 1024;
    const int tid = threadIdx.x;
    const int lane = tid & 31, wid = tid >> 5;
    const int wm = wid & 3, wn = wid >> 2;
    const int m0 = blockIdx.y * 128, n0 = blockIdx.x * 128;

    const char* srcs[3] = {
        Ath + (size_t)blockIdx.y * NCH * TILEB,
        Atl + (size_t)blockIdx.y * NCH * TILEB,
        Wth + (size_t)blockIdx.x * NCH * TILEB
    };

    if (tid == 0) { MBAR_INIT(mb0, 1u); MBAR_INIT(mb1, 1u); MBAR_INIT(mb2, 1u); }
    __syncthreads();

    const int aq = lane >> 3;
    const uint32_t a_row = (uint32_t)((aq & 1) * 8 + (lane & 7));
    const uint32_t a_colb = (uint32_t)((aq >> 1) * 16);
    const uint32_t b_row = (uint32_t)(((aq & 2) ? 8 : 0) + (lane & 7));
    const uint32_t b_colb = (uint32_t)((aq & 1) * 16);

    float acc[2][8][4];
#pragma unroll
    for (int mt = 0; mt < 2; mt++)
#pragma unroll
        for (int nt = 0; nt < 8; nt++)
#pragma unroll
            for (int e = 0; e < 4; e++) acc[mt][nt][e] = 0.f;

    if (tid == 0) {
#pragma unroll
        for (int c = 0; c < 2; c++) {
            uint32_t mbc = sb + 8u * c;
            MBAR_EXPECT_TX(mbc, (uint32_t)STGB);
#pragma unroll
            for (int p = 0; p < 3; p++)
                BULK_G2S(stage0 + c * STGB + p * TILEB, srcs[p] + (size_t)c * TILEB,
                         (uint32_t)TILEB, mbc);
        }
    }

    int s = 0, ph0 = 0, ph1 = 0, ph2v = 0;
    for (int t = 0; t < NCH; ++t) {
        if (t + 2 < NCH && tid == 0) {
            int s2 = s + 2; if (s2 >= 3) s2 -= 3;
            uint32_t mbn = sb + 8u * s2;
            uint32_t stn = stage0 + (uint32_t)(s2 * STGB);
            MBAR_EXPECT_TX(mbn, (uint32_t)STGB);
#pragma unroll
            for (int p = 0; p < 3; p++)
                BULK_G2S(stn + p * TILEB, srcs[p] + (size_t)(t + 2) * TILEB,
                         (uint32_t)TILEB, mbn);
        }
        if (s == 0)      { MBAR_WAIT(mb0, ph0); ph0 ^= 1; }
        else if (s == 1) { MBAR_WAIT(mb1, ph1); ph1 ^= 1; }
        else             { MBAR_WAIT(mb2, ph2v); ph2v ^= 1; }

        const uint32_t st = stage0 + (uint32_t)(s * STGB);
        const uint32_t aRow = (uint32_t)(wm * 32) + a_row;
        const uint32_t bRow = (uint32_t)(wn * 64) + b_row;

#pragma unroll
        for (int ks = 0; ks < 4; ++ks) {
            const uint32_t kb = (uint32_t)(ks * 32);
            uint32_t ah[2][4], al[2][4];
#pragma unroll
            for (int mt = 0; mt < 2; mt++) {
                uint32_t off = sw128((aRow + mt * 16) * 128 + kb + a_colb);
                ldm_x4(ah[mt], st + 0 * TILEB + off);
                ldm_x4(al[mt], st + 1 * TILEB + off);
            }
            uint32_t bh[8][2];
#pragma unroll
            for (int np = 0; np < 4; np++) {
                uint32_t off = sw128((bRow + np * 16) * 128 + kb + b_colb);
                uint32_t rh[4];
                ldm_x4(rh, st + 2 * TILEB + off);
                bh[np * 2][0] = rh[0]; bh[np * 2][1] = rh[1];
                bh[np * 2 + 1][0] = rh[2]; bh[np * 2 + 1][1] = rh[3];
            }
#pragma unroll
            for (int mt = 0; mt < 2; mt++)
#pragma unroll
                for (int nt = 0; nt < 8; nt++) {
                    mma_f16(acc[mt][nt], ah[mt], bh[nt]);
                    mma_f16(acc[mt][nt], al[mt], bh[nt]);
                }
        }
        __syncthreads();
        s = (s + 1 == 3) ? 0 : s + 1;
    }

    const int l4 = lane >> 2, l2 = (lane & 3) * 2;
    const int ncol0 = n0 + wn * 64;
#pragma unroll
    for (int mt = 0; mt < 2; mt++) {
        int m = m0 + wm * 32 + mt * 16 + l4;
        float* r0 = C + (size_t)m * H1DIM + ncol0;
        float* r1 = r0 + (size_t)8 * H1DIM;
#pragma unroll
        for (int nt = 0; nt < 8; nt++) {
            int col = nt * 8 + l2;
            float b0 = bias[ncol0 + col], b1 = bias[ncol0 + col + 1];
            float v0 = fmaxf(acc[mt][nt][0] + b0, 0.f);
            float v1 = fmaxf(acc[mt][nt][1] + b1, 0.f);
            float v2 = fmaxf(acc[mt][nt][2] + b0, 0.f);
            float v3 = fmaxf(acc[mt][nt][3] + b1, 0.f);
            *(float2*)&r0[col] = make_float2(v0, v1);
            *(float2*)&r1[col] = make_float2(v2, v3);
        }
    }
}

// -------- f32x2 packed FMA helpers (GEMM2) --------
__device__ __forceinline__ unsigned long long dup2(float x) {
    unsigned long long r; asm("mov.b64 %0, {%1, %1};" : "=l"(r) : "f"(x)); return r;
}
__device__ __forceinline__ void fma2(unsigned long long& d, unsigned long long a, unsigned long long b) {
    asm("fma.rn.f32x2 %0, %1, %2, %0;" : "+l"(d) : "l"(a), "l"(b));
}
__device__ __forceinline__ void unp2(unsigned long long v, float& lo, float& hi) {
    asm("mov.b64 {%0, %1}, %2;" : "=f"(lo), "=f"(hi) : "l"(v));
}

// -------- GEMM2 (fp32): BM=64, C = relu(A@B + b) -----
__global__ void __launch_bounds__(256)
gemm2_64(const float* __restrict__ A, const float* __restrict__ B,
         const float* __restrict__ bias, float* __restrict__ C,
         int M, int N, int K) {
    const int BKf = 16;
    __shared__ __align__(16) float As[2][16][72];
    __shared__ __align__(16) float Bs[2][16][128];

    const int tid = threadIdx.x;
    const int tx = tid & 15, ty = tid >> 4;
    const int m0 = blockIdx.y * 64, n0 = blockIdx.x * 128;
    const int ar0 = tid >> 2, ak0 = (tid & 3) * 4;
    const int br0 = tid >> 5, bc0 = (tid & 31) * 4;

    const float* Aptr = A + (size_t)(m0 + ar0) * K + ak0;
    const float* Bptr = B + (size_t)br0 * N + n0 + bc0;

    unsigned long long acc[4][4];
#pragma unroll
    for (int i = 0; i < 4; i++)
#pragma unroll
        for (int j = 0; j < 4; j++) acc[i][j] = 0ull;

    float4 a0f = *(const float4*)Aptr;
    float4 b0f = *(const float4*)Bptr;
    float4 b1f = *(const float4*)(Bptr + 8 * N);

    As[0][ak0+0][ar0] = a0f.x; As[0][ak0+1][ar0] = a0f.y;
    As[0][ak0+2][ar0] = a0f.z; As[0][ak0+3][ar0] = a0f.w;
    *(float4*)&Bs[0][br0][bc0] = b0f;
    *(float4*)&Bs[0][br0+8][bc0] = b1f;
    __syncthreads();

    const int nT = K / BKf;
    int buf = 0;
    for (int t = 0; t < nT; ++t) {
        if (t + 1 < nT) {
            a0f = *(const float4*)(Aptr + (t + 1) * BKf);
            const float* Bp = Bptr + (size_t)(t + 1) * BKf * N;
            b0f = *(const float4*)Bp;
            b1f = *(const float4*)(Bp + 8 * N);
        }
#pragma unroll
        for (int k = 0; k < BKf; ++k) {
            float4 av = *(const float4*)&As[buf][k][ty * 4];
            ulonglong2 bA = *(const ulonglong2*)&Bs[buf][k][tx * 8];
            ulonglong2 bB = *(const ulonglong2*)&Bs[buf][k][tx * 8 + 4];
            float avf[4] = {av.x, av.y, av.z, av.w};
#pragma unroll
            for (int i = 0; i < 4; i++) {
                unsigned long long ad = dup2(avf[i]);
                fma2(acc[i][0], ad, bA.x);
                fma2(acc[i][1], ad, bA.y);
                fma2(acc[i][2], ad, bB.x);
                fma2(acc[i][3], ad, bB.y);
            }
        }
        if (t + 1 < nT) {
            int nb = buf ^ 1;
            As[nb][ak0+0][ar0] = a0f.x; As[nb][ak0+1][ar0] = a0f.y;
            As[nb][ak0+2][ar0] = a0f.z; As[nb][ak0+3][ar0] = a0f.w;
            *(float4*)&Bs[nb][br0][bc0] = b0f;
            *(float4*)&Bs[nb][br0+8][bc0] = b1f;
        }
        __syncthreads();
        buf ^= 1;
    }

    float bb[8];
#pragma unroll
    for (int c = 0; c < 8; c++) bb[c] = bias[n0 + tx * 8 + c];
#pragma unroll
    for (int i = 0; i < 4; i++) {
        float* Crow = C + (size_t)(m0 + ty * 4 + i) * N + n0 + tx * 8;
#pragma unroll
        for (int j = 0; j < 4; j++) {
            float lo, hi; unp2(acc[i][j], lo, hi);
            lo = fmaxf(lo + bb[2*j], 0.f);
            hi = fmaxf(hi + bb[2*j+1], 0.f);
            *(float2*)&Crow[2*j] = make_float2(lo, hi);
        }
    }
}

// -------- primary caps: fused row-LN + einsum + bias + per-capsule LN ------
__global__ void __launch_bounds__(256)
prim_kernel(const float* __restrict__ h2, const float* __restrict__ lng,
            const float* __restrict__ lnb, const float* __restrict__ pcW,
            const float* __restrict__ pcB, const float* __restrict__ pcG,
            const float* __restrict__ pcBeta, float* __restrict__ prim) {
    __shared__ float hs[8 * 256];
    int tid = threadIdx.x;
    int row0 = blockIdx.x * 8;
    for (int i = tid; i < 2048; i += 256) hs[i] = h2[(size_t)row0 * 256 + i];
    __syncthreads();

    {
        int warp = tid >> 5, lane = tid & 31;
        float* xr = hs + warp * 256;
        float x[8];
#pragma unroll
        for (int e = 0; e < 8; e++) x[e] = xr[lane + 32 * e];
        float s = 0.f;
#pragma unroll
        for (int e = 0; e < 8; e++) s += x[e];
#pragma unroll
        for (int o = 16; o; o >>= 1) s += __shfl_xor_sync(~0u, s, o);
        float mu = s * (1.f / 256.f);
        float vs = 0.f;
#pragma unroll
        for (int e = 0; e < 8; e++) { float d = x[e] - mu; vs += d * d; }
#pragma unroll
        for (int o = 16; o; o >>= 1) vs += __shfl_xor_sync(~0u, vs, o);
        float inv = rsqrtf(vs * (1.f / 256.f) + 1e-5f);
#pragma unroll
        for (int e = 0; e < 8; e++) {
            int c = lane + 32 * e;
            xr[c] = (x[e] - mu) * inv * lng[c] + lnb[c];
        }
    }
    __syncthreads();

    int n = tid >> 3;
    float acc[8] = {0,0,0,0,0,0,0,0};
    const float* w = pcW + n * 2048 + (tid & 7);
    for (int c = 0; c < 256; c += 4) {
        float w0 = w[(c+0)*8], w1 = w[(c+1)*8], w2 = w[(c+2)*8], w3 = w[(c+3)*8];
#pragma unroll
        for (int r = 0; r < 8; r++)
            acc[r] += hs[r*256+c]*w0 + hs[r*256+c+1]*w1 + hs[r*256+c+2]*w2 + hs[r*256+c+3]*w3;
    }
    float bn = pcB[tid], gg = pcG[tid], bt = pcBeta[tid];
#pragma unroll
    for (int r = 0; r < 8; r++) {
        float x = acc[r] + bn;
        float s = x;
        s += __shfl_xor_sync(~0u, s, 1); s += __shfl_xor_sync(~0u, s, 2); s += __shfl_xor_sync(~0u, s, 4);
        float mu = s * 0.125f;
        float dv = x - mu;
        float v = dv * dv;
        v += __shfl_xor_sync(~0u, v, 1); v += __shfl_xor_sync(~0u, v, 2); v += __shfl_xor_sync(~0u, v, 4);
        float inv = rsqrtf(v * 0.125f + 1e-5f);
        prim[(size_t)(row0 + r) * 256 + tid] = dv * inv * gg + bt;
    }
}

// -------- predictions GEMM: 32 items/CTA, e8-units, STG.128 fp16 out -------
__global__ void __launch_bounds__(256)
pred_kernel(const float* __restrict__ prim, const float* __restrict__ dcW,
            __half* __restrict__ pred) {
    __shared__ float ps[32 * 256];
    const int tid = threadIdx.x;
    const int m0 = blockIdx.x * 32;
    for (int i = tid; i < 32 * 256 / 4; i += 256)
        ((float4*)ps)[i] = ((const float4*)(prim + (size_t)m0 * 256))[i];
    __syncthreads();

    for (int eg = 0; eg < 25; eg++) {
        int e8 = tid + eg * 256;
        int e = e8 * 8;
        int n = e / 1600;
        float4 w[16];
        const float4* wp = (const float4*)(dcW + (size_t)e * 8);
#pragma unroll
        for (int q = 0; q < 16; q++) w[q] = wp[q];
#pragma unroll 2
        for (int i = 0; i < 32; i++) {
            const float* p = ps + i * 256 + n * 8;
            float4 pa = *(const float4*)p;
            float4 pb = *(const float4*)(p + 4);
            float r[8];
#pragma unroll
            for (int q = 0; q < 8; q++) {
                r[q] = w[2*q].x*pa.x + w[2*q].y*pa.y + w[2*q].z*pa.z + w[2*q].w*pa.w
                     + w[2*q+1].x*pb.x + w[2*q+1].y*pb.y + w[2*q+1].z*pb.z + w[2*q+1].w*pb.w;
            }
            __half2 h0 = __floats2half2_rn(r[0], r[1]);
            __half2 h1 = __floats2half2_rn(r[2], r[3]);
            __half2 h2v = __floats2half2_rn(r[4], r[5]);
            __half2 h3 = __floats2half2_rn(r[6], r[7]);
            uint4 u;
            u.x = *(uint32_t*)&h0; u.y = *(uint32_t*)&h1;
            u.z = *(uint32_t*)&h2v; u.w = *(uint32_t*)&h3;
            *(uint4*)(pred + (size_t)(m0 + i) * NPRED + e) = u;
        }
    }
}

// -------- fused routing + logits; fp16 pred via bulk copy ------------------
__global__ void __launch_bounds__(1024)
routing_kernel(const __half* __restrict__ pred_g,
               const float* __restrict__ sf, const float* __restrict__ priors,
               const float* __restrict__ targets, const float* __restrict__ temp_p,
               float* __restrict__ out) {
    extern __shared__ float sm[];
    __half2* ph2 = (__half2*)sm;        // 25600 half2 = 25600 float slots
    float* bq   = sm + 25600;           // 3200
    float* vv   = bq + 3200;            // 1600
    float* sp   = vv + 1600;            // 128
    float* mrow = sp + 128;             // 32
    float* lse  = mrow + 32;            // 32
    float* red  = lse + 32;             // 128
    const uint32_t mbar = smem_u32(sm) + 30720u * 4u;

    const int bidx = blockIdx.x;
    const int tid = threadIdx.x;
    const int lane = tid & 31, warp = tid >> 5;

    if (tid == 0) MBAR_INIT(mbar, 1u);
    __syncthreads();
    if (tid == 0) {
        MBAR_EXPECT_TX(mbar, (uint32_t)(NPRED * 2));
        const char* src = (const char*)(pred_g + (size_t)bidx * NPRED);
        uint32_t dst = smem_u32(sm);
#pragma unroll
        for (int p = 0; p < 4; p++)
            BULK_G2S(dst + p * (NPRED / 2), src + (size_t)p * (NPRED / 2),
                     (uint32_t)(NPRED / 2), mbar);
    }

    if (tid < 100) red[tid] = fmaxf(sf[(size_t)bidx * 100 + tid], 0.f);
    __syncthreads();
    if (tid < 32) {
        float s = red[tid] + red[tid + 32] + red[tid + 64] + ((tid < 4) ? red[tid + 96] : 0.f);
#pragma unroll
        for (int o = 16; o; o >>= 1) s += __shfl_xor_sync(~0u, s, o);
        if (tid == 0) red[112] = s;
    }
    __syncthreads();
    float invs = 1.f / fmaxf(red[112], 1e-6f);
    __syncthreads();
    if (tid < 100) red[tid] = red[tid] * invs - 0.01f;
    __syncthreads();
    if (tid < 100) {
        float a = 0.f;
        for (int s = 0; s < 100; s++) a += red[s] * priors[s * 100 + tid];
        sp[tid] = a;
    }
    __syncthreads();

    for (int idx = tid; idx < 3200; idx += 1024) bq[idx] = sp[idx % 100] * 0.1f;

    MBAR_WAIT(mbar, 0);
    __syncthreads();

    for (int it = 0; it < 3; it++) {
        {
            float b0 = bq[warp * 100 + lane];
            float b1 = bq[warp * 100 + 32 + lane];
            float b2 = bq[warp * 100 + 64 + lane];
            float b3 = (lane < 4) ? bq[warp * 100 + 96 + lane] : -1e30f;
            float m = fmaxf(fmaxf(b0, b1), fmaxf(b2, b3));
#pragma unroll
            for (int o = 16; o; o >>= 1) m = fmaxf(m, __shfl_xor_sync(~0u, m, o));
            float e0 = __expf(b0 - m), e1 = __expf(b1 - m), e2 = __expf(b2 - m);
            float e3 = (lane < 4) ? __expf(b3 - m) : 0.f;
            float s = e0 + e1 + e2 + e3;
#pragma unroll
            for (int o = 16; o; o >>= 1) s += __shfl_xor_sync(~0u, s, o);
            float is = 1.f / s;
            bq[warp * 100 + lane]      = e0 * is;
            bq[warp * 100 + 32 + lane] = e1 * is;
            bq[warp * 100 + 64 + lane] = e2 * is;
            if (lane < 4) bq[warp * 100 + 96 + lane] = e3 * is;
            if (lane == 0) { mrow[warp] = m; lse[warp] = __logf(s); }
        }
        __syncthreads();

        if (tid < 800) {
            int j = tid >> 3;
            float s0 = 0.f, s1 = 0.f;
#pragma unroll 8
            for (int n = 0; n < 32; n++) {
                float c = bq[n * 100 + j];
                float2 p = __half22float2(ph2[n * 800 + tid]);
                s0 += c * p.x; s1 += c * p.y;
            }
            int o2 = (tid & 7) * 2;
            vv[j * 16 + o2] = s0;
            vv[j * 16 + o2 + 1] = s1;
        }
        __syncthreads();
        if (tid < 100) {
            float sq = 0.f;
#pragma unroll
            for (int o = 0; o < 16; o++) { float t = vv[tid * 16 + o]; sq += t * t; }
            red[tid] = (sq / (1.f + sq)) * rsqrtf(sq + 1e-8f);
        }
        __syncthreads();
        for (int idx = tid; idx < 1600; idx += 1024) vv[idx] *= red[idx >> 4];
        __syncthreads();

        if (it < 2) {
            float strength = 0.1f - 0.02f * (it + 1);
            for (int idx = tid; idx < 3200; idx += 1024) {
                int n = idx / 100, j = idx - n * 100;
                float c = bq[idx];
                const __half2* pp = ph2 + n * 800 + j * 8;
                float dot = 0.f;
#pragma unroll
                for (int op = 0; op < 8; op++) {
                    float2 p = __half22float2(pp[op]);
                    dot += p.x * vv[j * 16 + op * 2] + p.y * vv[j * 16 + op * 2 + 1];
                }
                bq[idx] = __logf(fmaxf(c, 1e-38f)) + mrow[n] + lse[n] + dot + sp[j] * strength;
            }
            __syncthreads();
        }
    }

    if (tid < 100) {
        float nr = 0.f, dt = 0.f;
#pragma unroll
        for (int o = 0; o < 16; o++) {
            float v = vv[tid * 16 + o];
            nr += v * v;
            dt += v * targets[tid * 16 + o];
        }
        out[(size_t)bidx * 100 + tid] = temp_p[0] * dt / fmaxf(sqrtf(nr), 1e-12f);
    }
}

extern "C" void kernel_launch(void* const* d_in, const int* in_sizes, int n_in,
                              void* d_out, int out_size) {
    const float* features = (const float*)d_in[0];
    const float* slot_f   = (const float*)d_in[1];
    const float* W1       = (const float*)d_in[2];
    const float* b1       = (const float*)d_in[3];
    const float* W2       = (const float*)d_in[4];
    const float* b2       = (const float*)d_in[5];
    const float* ln_g     = (const float*)d_in[6];
    const float* ln_b     = (const float*)d_in[7];
    const float* pc_W     = (const float*)d_in[8];
    const float* pc_b     = (const float*)d_in[9];
    const float* pc_g     = (const float*)d_in[10];
    const float* pc_beta  = (const float*)d_in[11];
    const float* dc_W     = (const float*)d_in[12];
    const float* priors   = (const float*)d_in[13];
    const float* targets  = (const float*)d_in[14];
    const float* temp     = (const float*)d_in[15];
    float* out = (float*)d_out;

    float* h1; cudaGetSymbolAddress((void**)&h1, g_h1);
    float* h2; cudaGetSymbolAddress((void**)&h2, g_h2);
    float* pr; cudaGetSymbolAddress((void**)&pr, g_prim);
    __half* pd; cudaGetSymbolAddress((void**)&pd, g_pred);
    char* Ah; cudaGetSymbolAddress((void**)&Ah, g_Ahi);
    char* Al; cudaGetSymbolAddress((void**)&Al, g_Alo);
    char* Wh; cudaGetSymbolAddress((void**)&Wh, g_Whi);

    const int RSMEM = 30720 * 4 + 32;     // 122912 B
    cudaFuncSetAttribute(routing_kernel, cudaFuncAttributeMaxDynamicSharedMemorySize, RSMEM);
    const int GSMEM = 1024 + 3 * STGB;    // 148480 B
    cudaFuncSetAttribute(gemm1_mma, cudaFuncAttributeMaxDynamicSharedMemorySize, GSMEM);

    splitA<<<dim3((KP / 8 + 255) / 256, BATCH), 256>>>(features, Ah, Al);
    splitW<<<dim3(KP / 32, H1DIM / 32), 256>>>(W1, Wh);
    gemm1_mma<<<dim3(H1DIM / 128, BATCH / 128), 256, GSMEM>>>(Ah, Al, Wh, b1, h1);
    gemm2_64<<<dim3(256 / 128, 4096 / 64), 256>>>(h1, W2, b2, h2, 4096, 256, 512);
    prim_kernel<<<512, 256>>>(h2, ln_g, ln_b, pc_W, pc_b, pc_g, pc_beta, pr);
    pred_kernel<<<BATCH / 32, 256>>>(pr, dc_W, pd);
    routing_kernel<<<4096, 1024, RSMEM>>>(pd, slot_f, priors, targets, temp, out);
}

// round 15
// speedup vs baseline: 1.4862x; 1.2052x over previous
#include <cuda_runtime.h>
#include <cuda_fp16.h>
#include <math.h>
#include <stdint.h>

#define BATCH  4096
#define IN_DIM 20000
#define H1DIM  512
#define H2DIM  256
#define NCAPS  32
#define PDIM   8
#define CDIM   16
#define NLAB   100

#define KP     20032            // IN_DIM padded to 313*64
#define NCH    313              // chunks
#define TILEB  16384            // one tile: 128 rows x 128 B (swizzled), contiguous
#define STGB   (2 * TILEB)      // stage: A, W
#define NPRED  51200            // 32*100*16 per item

__device__ float g_h1[BATCH * H1DIM];
__device__ float g_h2[BATCH * H2DIM];
__device__ float g_prim[BATCH * NCAPS * PDIM];
__device__ __half g_pred[(size_t)BATCH * NPRED];
// tiled, pre-swizzled fp16 buffers
__device__ __align__(128) char g_Ahi[(size_t)32 * NCH * TILEB];
__device__ __align__(128) char g_Whi[(size_t)4 * NCH * TILEB];

// ---------------- helpers ----------------
__device__ __forceinline__ uint32_t smem_u32(const void* p) {
    uint32_t a;
    asm("{ .reg .u64 t; cvta.to.shared.u64 t, %1; cvt.u32.u64 %0, t; }" : "=r"(a) : "l"(p));
    return a;
}
__device__ __forceinline__ uint32_t sw128(uint32_t off) {
    return off ^ ((off >> 3) & 0x70);
}
__device__ __forceinline__ void ldm_x4(uint32_t* r, uint32_t addr) {
    asm volatile("ldmatrix.sync.aligned.m8n8.x4.shared.b16 {%0,%1,%2,%3}, [%4];"
                 : "=r"(r[0]), "=r"(r[1]), "=r"(r[2]), "=r"(r[3]) : "r"(addr));
}
__device__ __forceinline__ void mma_f16(float* c, const uint32_t* a, const uint32_t* b) {
    asm volatile("mma.sync.aligned.m16n8k16.row.col.f32.f16.f16.f32 "
                 "{%0,%1,%2,%3}, {%4,%5,%6,%7}, {%8,%9}, {%0,%1,%2,%3};"
                 : "+f"(c[0]), "+f"(c[1]), "+f"(c[2]), "+f"(c[3])
                 : "r"(a[0]), "r"(a[1]), "r"(a[2]), "r"(a[3]), "r"(b[0]), "r"(b[1]));
}
__device__ __forceinline__ uint32_t pack_h2(__half a, __half b) {
    __half2 t; t.x = a; t.y = b;
    return *(uint32_t*)&t;
}
#define MBAR_INIT(a, c) asm volatile("mbarrier.init.shared.b64 [%0], %1;" :: "r"(a), "r"(c) : "memory")
#define MBAR_EXPECT_TX(a, b) asm volatile("mbarrier.arrive.expect_tx.shared.b64 _, [%0], %1;" :: "r"(a), "r"(b) : "memory")
#define BULK_G2S(dst, src, sz, mbar) \
    asm volatile("cp.async.bulk.shared::cluster.global.mbarrier::complete_tx::bytes [%0], [%1], %2, [%3];" \
                 :: "r"(dst), "l"(src), "r"(sz), "r"(mbar) : "memory")

#define MBAR_WAIT(mbar_smem_addr, phase_parity) do { \
    uint32_t _mbar = (uint32_t)(mbar_smem_addr); \
    uint32_t _parity = (uint32_t)(phase_parity); \
    uint32_t _done; \
    asm volatile( \
        "{\n\t.reg .pred p;\n\t" \
        "mbarrier.try_wait.parity.acquire.cta.shared::cta.b64 p, [%1], %2;\n\t" \
        "selp.b32 %0, 1, 0, p;\n\t}" \
        : "=r"(_done) : "r"(_mbar), "r"(_parity) : "memory"); \
    if (!_done) { \
        asm volatile( \
            "{\n\t.reg .pred P1;\n\t" \
            "WAIT_LOOP_%=:\n\t" \
            "mbarrier.try_wait.parity.acquire.cta.shared::cta.b64 P1, [%0], %1, 0x989680;\n\t" \
            "@P1 bra.uni WAIT_DONE_%=;\n\t" \
            "bra.uni WAIT_LOOP_%=;\n\t" \
            "WAIT_DONE_%=:\n\t}" \
            :: "r"(_mbar), "r"(_parity) : "memory"); \
    } \
} while(0)

// ---------------- prep: features -> tiled swizzled fp16 --------------------
__global__ void __launch_bounds__(256)
splitA(const float* __restrict__ F, char* __restrict__ Ah) {
    int m = blockIdx.y;
    int u = blockIdx.x * 256 + threadIdx.x;
    if (u >= KP / 8) return;
    int k0 = u * 8;
    float v[8];
    if (k0 < IN_DIM) {
        const float4* fp = (const float4*)(F + (size_t)m * IN_DIM + k0);
        float4 f0 = fp[0], f1 = fp[1];
        v[0]=f0.x; v[1]=f0.y; v[2]=f0.z; v[3]=f0.w;
        v[4]=f1.x; v[5]=f1.y; v[6]=f1.z; v[7]=f1.w;
    } else {
#pragma unroll
        for (int j = 0; j < 8; j++) v[j] = 0.f;
    }
    uint32_t hi[4];
#pragma unroll
    for (int j = 0; j < 4; j++)
        hi[j] = pack_h2(__float2half_rn(v[2*j]), __float2half_rn(v[2*j+1]));
    int mt = m >> 7, row = m & 127, ch = u >> 3, u8 = u & 7;
    uint32_t off = sw128((uint32_t)(row * 128 + u8 * 16));
    size_t addr = ((size_t)mt * NCH + ch) * TILEB + off;
    *(uint4*)(Ah + addr) = make_uint4(hi[0], hi[1], hi[2], hi[3]);
}

// ---------------- prep: transpose W1 [K,N] -> tiled swizzled fp16 ----------
__global__ void __launch_bounds__(256)
splitW(const float* __restrict__ W1, char* __restrict__ Wh) {
    __shared__ float ts[32][33];
    int k0 = blockIdx.x * 32, n0 = blockIdx.y * 32;
    int tx = threadIdx.x & 31, ty = threadIdx.x >> 5;
#pragma unroll
    for (int r = 0; r < 32; r += 8) {
        int k = k0 + ty + r;
        ts[ty + r][tx] = (k < IN_DIM) ? W1[(size_t)k * H1DIM + n0 + tx] : 0.f;
    }
    __syncthreads();
#pragma unroll
    for (int r = 0; r < 32; r += 8) {
        int n = n0 + ty + r;
        int k = k0 + tx;
        float x = ts[tx][ty + r];
        int nt = n >> 7, row = n & 127, ch = k >> 6, kk = k & 63;
        uint32_t off = sw128((uint32_t)(row * 128 + kk * 2));
        size_t addr = ((size_t)nt * NCH + ch) * TILEB + off;
        *(__half*)(Wh + addr) = __float2half_rn(x);
    }
}

// ---------------- GEMM1: 3-stage bulk-TMA + mma.sync fp16 ------------------
__global__ void __launch_bounds__(256)
gemm1_mma(const char* __restrict__ Ath, const char* __restrict__ Wth,
          const float* __restrict__ bias, float* __restrict__ C) {
    extern __shared__ __align__(1024) char smem[];
    const uint32_t sb = smem_u32(smem);
    const uint32_t mb0 = sb, mb1 = sb + 8, mb2 = sb + 16;
    const uint32_t stage0 = sb + 1024;
    const int tid = threadIdx.x;
    const int lane = tid & 31, wid = tid >> 5;
    const int wm = wid & 3, wn = wid >> 2;
    const int m0 = blockIdx.y * 128, n0 = blockIdx.x * 128;

    const char* srcs[2] = {
        Ath + (size_t)blockIdx.y * NCH * TILEB,
        Wth + (size_t)blockIdx.x * NCH * TILEB
    };

    if (tid == 0) { MBAR_INIT(mb0, 1u); MBAR_INIT(mb1, 1u); MBAR_INIT(mb2, 1u); }
    __syncthreads();

    const int aq = lane >> 3;
    const uint32_t a_row = (uint32_t)((aq & 1) * 8 + (lane & 7));
    const uint32_t a_colb = (uint32_t)((aq >> 1) * 16);
    const uint32_t b_row = (uint32_t)(((aq & 2) ? 8 : 0) + (lane & 7));
    const uint32_t b_colb = (uint32_t)((aq & 1) * 16);

    float acc[2][8][4];
#pragma unroll
    for (int mt = 0; mt < 2; mt++)
#pragma unroll
        for (int nt = 0; nt < 8; nt++)
#pragma unroll
            for (int e = 0; e < 4; e++) acc[mt][nt][e] = 0.f;

    if (tid == 0) {
#pragma unroll
        for (int c = 0; c < 2; c++) {
            uint32_t mbc = sb + 8u * c;
            MBAR_EXPECT_TX(mbc, (uint32_t)STGB);
#pragma unroll
            for (int p = 0; p < 2; p++)
                BULK_G2S(stage0 + c * STGB + p * TILEB, srcs[p] + (size_t)c * TILEB,
                         (uint32_t)TILEB, mbc);
        }
    }

    int s = 0, ph0 = 0, ph1 = 0, ph2v = 0;
    for (int t = 0; t < NCH; ++t) {
        if (t + 2 < NCH && tid == 0) {
            int s2 = s + 2; if (s2 >= 3) s2 -= 3;
            uint32_t mbn = sb + 8u * s2;
            uint32_t stn = stage0 + (uint32_t)(s2 * STGB);
            MBAR_EXPECT_TX(mbn, (uint32_t)STGB);
#pragma unroll
            for (int p = 0; p < 2; p++)
                BULK_G2S(stn + p * TILEB, srcs[p] + (size_t)(t + 2) * TILEB,
                         (uint32_t)TILEB, mbn);
        }
        if (s == 0)      { MBAR_WAIT(mb0, ph0); ph0 ^= 1; }
        else if (s == 1) { MBAR_WAIT(mb1, ph1); ph1 ^= 1; }
        else             { MBAR_WAIT(mb2, ph2v); ph2v ^= 1; }

        const uint32_t st = stage0 + (uint32_t)(s * STGB);
        const uint32_t aRow = (uint32_t)(wm * 32) + a_row;
        const uint32_t bRow = (uint32_t)(wn * 64) + b_row;

#pragma unroll
        for (int ks = 0; ks < 4; ++ks) {
            const uint32_t kb = (uint32_t)(ks * 32);
            uint32_t ah[2][4];
#pragma unroll
            for (int mt = 0; mt < 2; mt++) {
                uint32_t off = sw128((aRow + mt * 16) * 128 + kb + a_colb);
                ldm_x4(ah[mt], st + 0 * TILEB + off);
            }
            uint32_t bh[8][2];
#pragma unroll
            for (int np = 0; np < 4; np++) {
                uint32_t off = sw128((bRow + np * 16) * 128 + kb + b_colb);
                uint32_t rh[4];
                ldm_x4(rh, st + 1 * TILEB + off);
                bh[np * 2][0] = rh[0]; bh[np * 2][1] = rh[1];
                bh[np * 2 + 1][0] = rh[2]; bh[np * 2 + 1][1] = rh[3];
            }
#pragma unroll
            for (int mt = 0; mt < 2; mt++)
#pragma unroll
                for (int nt = 0; nt < 8; nt++)
                    mma_f16(acc[mt][nt], ah[mt], bh[nt]);
        }
        __syncthreads();
        s = (s + 1 == 3) ? 0 : s + 1;
    }

    const int l4 = lane >> 2, l2 = (lane & 3) * 2;
    const int ncol0 = n0 + wn * 64;
#pragma unroll
    for (int mt = 0; mt < 2; mt++) {
        int m = m0 + wm * 32 + mt * 16 + l4;
        float* r0 = C + (size_t)m * H1DIM + ncol0;
        float* r1 = r0 + (size_t)8 * H1DIM;
#pragma unroll
        for (int nt = 0; nt < 8; nt++) {
            int col = nt * 8 + l2;
            float b0 = bias[ncol0 + col], b1 = bias[ncol0 + col + 1];
            float v0 = fmaxf(acc[mt][nt][0] + b0, 0.f);
            float v1 = fmaxf(acc[mt][nt][1] + b1, 0.f);
            float v2 = fmaxf(acc[mt][nt][2] + b0, 0.f);
            float v3 = fmaxf(acc[mt][nt][3] + b1, 0.f);
            *(float2*)&r0[col] = make_float2(v0, v1);
            *(float2*)&r1[col] = make_float2(v2, v3);
        }
    }
}

// -------- f32x2 packed FMA helpers (GEMM2) --------
__device__ __forceinline__ unsigned long long dup2(float x) {
    unsigned long long r; asm("mov.b64 %0, {%1, %1};" : "=l"(r) : "f"(x)); return r;
}
__device__ __forceinline__ void fma2(unsigned long long& d, unsigned long long a, unsigned long long b) {
    asm("fma.rn.f32x2 %0, %1, %2, %0;" : "+l"(d) : "l"(a), "l"(b));
}
__device__ __forceinline__ void unp2(unsigned long long v, float& lo, float& hi) {
    asm("mov.b64 {%0, %1}, %2;" : "=f"(lo), "=f"(hi) : "l"(v));
}

// -------- GEMM2 (fp32): BM=64, C = relu(A@B + b) -----
__global__ void __launch_bounds__(256)
gemm2_64(const float* __restrict__ A, const float* __restrict__ B,
         const float* __restrict__ bias, float* __restrict__ C,
         int M, int N, int K) {
    const int BKf = 16;
    __shared__ __align__(16) float As[2][16][72];
    __shared__ __align__(16) float Bs[2][16][128];

    const int tid = threadIdx.x;
    const int tx = tid & 15, ty = tid >> 4;
    const int m0 = blockIdx.y * 64, n0 = blockIdx.x * 128;
    const int ar0 = tid >> 2, ak0 = (tid & 3) * 4;
    const int br0 = tid >> 5, bc0 = (tid & 31) * 4;

    const float* Aptr = A + (size_t)(m0 + ar0) * K + ak0;
    const float* Bptr = B + (size_t)br0 * N + n0 + bc0;

    unsigned long long acc[4][4];
#pragma unroll
    for (int i = 0; i < 4; i++)
#pragma unroll
        for (int j = 0; j < 4; j++) acc[i][j] = 0ull;

    float4 a0f = *(const float4*)Aptr;
    float4 b0f = *(const float4*)Bptr;
    float4 b1f = *(const float4*)(Bptr + 8 * N);

    As[0][ak0+0][ar0] = a0f.x; As[0][ak0+1][ar0] = a0f.y;
    As[0][ak0+2][ar0] = a0f.z; As[0][ak0+3][ar0] = a0f.w;
    *(float4*)&Bs[0][br0][bc0] = b0f;
    *(float4*)&Bs[0][br0+8][bc0] = b1f;
    __syncthreads();

    const int nT = K / BKf;
    int buf = 0;
    for (int t = 0; t < nT; ++t) {
        if (t + 1 < nT) {
            a0f = *(const float4*)(Aptr + (t + 1) * BKf);
            const float* Bp = Bptr + (size_t)(t + 1) * BKf * N;
            b0f = *(const float4*)Bp;
            b1f = *(const float4*)(Bp + 8 * N);
        }
#pragma unroll
        for (int k = 0; k < BKf; ++k) {
            float4 av = *(const float4*)&As[buf][k][ty * 4];
            ulonglong2 bA = *(const ulonglong2*)&Bs[buf][k][tx * 8];
            ulonglong2 bB = *(const ulonglong2*)&Bs[buf][k][tx * 8 + 4];
            float avf[4] = {av.x, av.y, av.z, av.w};
#pragma unroll
            for (int i = 0; i < 4; i++) {
                unsigned long long ad = dup2(avf[i]);
                fma2(acc[i][0], ad, bA.x);
                fma2(acc[i][1], ad, bA.y);
                fma2(acc[i][2], ad, bB.x);
                fma2(acc[i][3], ad, bB.y);
            }
        }
        if (t + 1 < nT) {
            int nb = buf ^ 1;
            As[nb][ak0+0][ar0] = a0f.x; As[nb][ak0+1][ar0] = a0f.y;
            As[nb][ak0+2][ar0] = a0f.z; As[nb][ak0+3][ar0] = a0f.w;
            *(float4*)&Bs[nb][br0][bc0] = b0f;
            *(float4*)&Bs[nb][br0+8][bc0] = b1f;
        }
        __syncthreads();
        buf ^= 1;
    }

    float bb[8];
#pragma unroll
    for (int c = 0; c < 8; c++) bb[c] = bias[n0 + tx * 8 + c];
#pragma unroll
    for (int i = 0; i < 4; i++) {
        float* Crow = C + (size_t)(m0 + ty * 4 + i) * N + n0 + tx * 8;
#pragma unroll
        for (int j = 0; j < 4; j++) {
            float lo, hi; unp2(acc[i][j], lo, hi);
            lo = fmaxf(lo + bb[2*j], 0.f);
            hi = fmaxf(hi + bb[2*j+1], 0.f);
            *(float2*)&Crow[2*j] = make_float2(lo, hi);
        }
    }
}

// -------- primary caps: fused row-LN + einsum + bias + per-capsule LN ------
__global__ void __launch_bounds__(256)
prim_kernel(const float* __restrict__ h2, const float* __restrict__ lng,
            const float* __restrict__ lnb, const float* __restrict__ pcW,
            const float* __restrict__ pcB, const float* __restrict__ pcG,
            const float* __restrict__ pcBeta, float* __restrict__ prim) {
    __shared__ float hs[8 * 256];
    int tid = threadIdx.x;
    int row0 = blockIdx.x * 8;
    for (int i = tid; i < 2048; i += 256) hs[i] = h2[(size_t)row0 * 256 + i];
    __syncthreads();

    {
        int warp = tid >> 5, lane = tid & 31;
        float* xr = hs + warp * 256;
        float x[8];
#pragma unroll
        for (int e = 0; e < 8; e++) x[e] = xr[lane + 32 * e];
        float s = 0.f;
#pragma unroll
        for (int e = 0; e < 8; e++) s += x[e];
#pragma unroll
        for (int o = 16; o; o >>= 1) s += __shfl_xor_sync(~0u, s, o);
        float mu = s * (1.f / 256.f);
        float vs = 0.f;
#pragma unroll
        for (int e = 0; e < 8; e++) { float d = x[e] - mu; vs += d * d; }
#pragma unroll
        for (int o = 16; o; o >>= 1) vs += __shfl_xor_sync(~0u, vs, o);
        float inv = rsqrtf(vs * (1.f / 256.f) + 1e-5f);
#pragma unroll
        for (int e = 0; e < 8; e++) {
            int c = lane + 32 * e;
            xr[c] = (x[e] - mu) * inv * lng[c] + lnb[c];
        }
    }
    __syncthreads();

    int n = tid >> 3;
    float acc[8] = {0,0,0,0,0,0,0,0};
    const float* w = pcW + n * 2048 + (tid & 7);
    for (int c = 0; c < 256; c += 4) {
        float w0 = w[(c+0)*8], w1 = w[(c+1)*8], w2 = w[(c+2)*8], w3 = w[(c+3)*8];
#pragma unroll
        for (int r = 0; r < 8; r++)
            acc[r] += hs[r*256+c]*w0 + hs[r*256+c+1]*w1 + hs[r*256+c+2]*w2 + hs[r*256+c+3]*w3;
    }
    float bn = pcB[tid], gg = pcG[tid], bt = pcBeta[tid];
#pragma unroll
    for (int r = 0; r < 8; r++) {
        float x = acc[r] + bn;
        float s = x;
        s += __shfl_xor_sync(~0u, s, 1); s += __shfl_xor_sync(~0u, s, 2); s += __shfl_xor_sync(~0u, s, 4);
        float mu = s * 0.125f;
        float dv = x - mu;
        float v = dv * dv;
        v += __shfl_xor_sync(~0u, v, 1); v += __shfl_xor_sync(~0u, v, 2); v += __shfl_xor_sync(~0u, v, 4);
        float inv = rsqrtf(v * 0.125f + 1e-5f);
        prim[(size_t)(row0 + r) * 256 + tid] = dv * inv * gg + bt;
    }
}

// -------- predictions GEMM: 32 items/CTA, e8-units, STG.128 fp16 out -------
__global__ void __launch_bounds__(256)
pred_kernel(const float* __restrict__ prim, const float* __restrict__ dcW,
            __half* __restrict__ pred) {
    __shared__ float ps[32 * 256];
    const int tid = threadIdx.x;
    const int m0 = blockIdx.x * 32;
    for (int i = tid; i < 32 * 256 / 4; i += 256)
        ((float4*)ps)[i] = ((const float4*)(prim + (size_t)m0 * 256))[i];
    __syncthreads();

    for (int eg = 0; eg < 25; eg++) {
        int e8 = tid + eg * 256;
        int e = e8 * 8;
        int n = e / 1600;
        float4 w[16];
        const float4* wp = (const float4*)(dcW + (size_t)e * 8);
#pragma unroll
        for (int q = 0; q < 16; q++) w[q] = wp[q];
#pragma unroll 2
        for (int i = 0; i < 32; i++) {
            const float* p = ps + i * 256 + n * 8;
            float4 pa = *(const float4*)p;
            float4 pb = *(const float4*)(p + 4);
            float r[8];
#pragma unroll
            for (int q = 0; q < 8; q++) {
                r[q] = w[2*q].x*pa.x + w[2*q].y*pa.y + w[2*q].z*pa.z + w[2*q].w*pa.w
                     + w[2*q+1].x*pb.x + w[2*q+1].y*pb.y + w[2*q+1].z*pb.z + w[2*q+1].w*pb.w;
            }
            __half2 h0 = __floats2half2_rn(r[0], r[1]);
            __half2 h1 = __floats2half2_rn(r[2], r[3]);
            __half2 h2v = __floats2half2_rn(r[4], r[5]);
            __half2 h3 = __floats2half2_rn(r[6], r[7]);
            uint4 u;
            u.x = *(uint32_t*)&h0; u.y = *(uint32_t*)&h1;
            u.z = *(uint32_t*)&h2v; u.w = *(uint32_t*)&h3;
            *(uint4*)(pred + (size_t)(m0 + i) * NPRED + e) = u;
        }
    }
}

// -------- fused routing + logits; fp16 pred via bulk copy ------------------
__global__ void __launch_bounds__(1024)
routing_kernel(const __half* __restrict__ pred_g,
               const float* __restrict__ sf, const float* __restrict__ priors,
               const float* __restrict__ targets, const float* __restrict__ temp_p,
               float* __restrict__ out) {
    extern __shared__ float sm[];
    __half2* ph2 = (__half2*)sm;        // 25600 half2 = 25600 float slots
    float* bq   = sm + 25600;           // 3200
    float* vv   = bq + 3200;            // 1600
    float* sp   = vv + 1600;            // 128
    float* mrow = sp + 128;             // 32
    float* lse  = mrow + 32;            // 32
    float* red  = lse + 32;             // 128
    const uint32_t mbar = smem_u32(sm) + 30720u * 4u;

    const int bidx = blockIdx.x;
    const int tid = threadIdx.x;
    const int lane = tid & 31, warp = tid >> 5;

    if (tid == 0) MBAR_INIT(mbar, 1u);
    __syncthreads();
    if (tid == 0) {
        MBAR_EXPECT_TX(mbar, (uint32_t)(NPRED * 2));
        const char* src = (const char*)(pred_g + (size_t)bidx * NPRED);
        uint32_t dst = smem_u32(sm);
#pragma unroll
        for (int p = 0; p < 4; p++)
            BULK_G2S(dst + p * (NPRED / 2), src + (size_t)p * (NPRED / 2),
                     (uint32_t)(NPRED / 2), mbar);
    }

    if (tid < 100) red[tid] = fmaxf(sf[(size_t)bidx * 100 + tid], 0.f);
    __syncthreads();
    if (tid < 32) {
        float s = red[tid] + red[tid + 32] + red[tid + 64] + ((tid < 4) ? red[tid + 96] : 0.f);
#pragma unroll
        for (int o = 16; o; o >>= 1) s += __shfl_xor_sync(~0u, s, o);
        if (tid == 0) red[112] = s;
    }
    __syncthreads();
    float invs = 1.f / fmaxf(red[112], 1e-6f);
    __syncthreads();
    if (tid < 100) red[tid] = red[tid] * invs - 0.01f;
    __syncthreads();
    if (tid < 100) {
        float a = 0.f;
        for (int s = 0; s < 100; s++) a += red[s] * priors[s * 100 + tid];
        sp[tid] = a;
    }
    __syncthreads();

    for (int idx = tid; idx < 3200; idx += 1024) bq[idx] = sp[idx % 100] * 0.1f;

    MBAR_WAIT(mbar, 0);
    __syncthreads();

    for (int it = 0; it < 3; it++) {
        {
            float b0 = bq[warp * 100 + lane];
            float b1 = bq[warp * 100 + 32 + lane];
            float b2 = bq[warp * 100 + 64 + lane];
            float b3 = (lane < 4) ? bq[warp * 100 + 96 + lane] : -1e30f;
            float m = fmaxf(fmaxf(b0, b1), fmaxf(b2, b3));
#pragma unroll
            for (int o = 16; o; o >>= 1) m = fmaxf(m, __shfl_xor_sync(~0u, m, o));
            float e0 = __expf(b0 - m), e1 = __expf(b1 - m), e2 = __expf(b2 - m);
            float e3 = (lane < 4) ? __expf(b3 - m) : 0.f;
            float s = e0 + e1 + e2 + e3;
#pragma unroll
            for (int o = 16; o; o >>= 1) s += __shfl_xor_sync(~0u, s, o);
            float is = 1.f / s;
            bq[warp * 100 + lane]      = e0 * is;
            bq[warp * 100 + 32 + lane] = e1 * is;
            bq[warp * 100 + 64 + lane] = e2 * is;
            if (lane < 4) bq[warp * 100 + 96 + lane] = e3 * is;
            if (lane == 0) { mrow[warp] = m; lse[warp] = __logf(s); }
        }
        __syncthreads();

        if (tid < 800) {
            int j = tid >> 3;
            float s0 = 0.f, s1 = 0.f;
#pragma unroll 8
            for (int n = 0; n < 32; n++) {
                float c = bq[n * 100 + j];
                float2 p = __half22float2(ph2[n * 800 + tid]);
                s0 += c * p.x; s1 += c * p.y;
            }
            int o2 = (tid & 7) * 2;
            vv[j * 16 + o2] = s0;
            vv[j * 16 + o2 + 1] = s1;
        }
        __syncthreads();
        if (tid < 100) {
            float sq = 0.f;
#pragma unroll
            for (int o = 0; o < 16; o++) { float t = vv[tid * 16 + o]; sq += t * t; }
            red[tid] = (sq / (1.f + sq)) * rsqrtf(sq + 1e-8f);
        }
        __syncthreads();
        for (int idx = tid; idx < 1600; idx += 1024) vv[idx] *= red[idx >> 4];
        __syncthreads();

        if (it < 2) {
            float strength = 0.1f - 0.02f * (it + 1);
            for (int idx = tid; idx < 3200; idx += 1024) {
                int n = idx / 100, j = idx - n * 100;
                float c = bq[idx];
                const __half2* pp = ph2 + n * 800 + j * 8;
                float dot = 0.f;
#pragma unroll
                for (int op = 0; op < 8; op++) {
                    float2 p = __half22float2(pp[op]);
                    dot += p.x * vv[j * 16 + op * 2] + p.y * vv[j * 16 + op * 2 + 1];
                }
                bq[idx] = __logf(fmaxf(c, 1e-38f)) + mrow[n] + lse[n] + dot + sp[j] * strength;
            }
            __syncthreads();
        }
    }

    if (tid < 100) {
        float nr = 0.f, dt = 0.f;
#pragma unroll
        for (int o = 0; o < 16; o++) {
            float v = vv[tid * 16 + o];
            nr += v * v;
            dt += v * targets[tid * 16 + o];
        }
        out[(size_t)bidx * 100 + tid] = temp_p[0] * dt / fmaxf(sqrtf(nr), 1e-12f);
    }
}

extern "C" void kernel_launch(void* const* d_in, const int* in_sizes, int n_in,
                              void* d_out, int out_size) {
    const float* features = (const float*)d_in[0];
    const float* slot_f   = (const float*)d_in[1];
    const float* W1       = (const float*)d_in[2];
    const float* b1       = (const float*)d_in[3];
    const float* W2       = (const float*)d_in[4];
    const float* b2       = (const float*)d_in[5];
    const float* ln_g     = (const float*)d_in[6];
    const float* ln_b     = (const float*)d_in[7];
    const float* pc_W     = (const float*)d_in[8];
    const float* pc_b     = (const float*)d_in[9];
    const float* pc_g     = (const float*)d_in[10];
    const float* pc_beta  = (const float*)d_in[11];
    const float* dc_W     = (const float*)d_in[12];
    const float* priors   = (const float*)d_in[13];
    const float* targets  = (const float*)d_in[14];
    const float* temp     = (const float*)d_in[15];
    float* out = (float*)d_out;

    float* h1; cudaGetSymbolAddress((void**)&h1, g_h1);
    float* h2; cudaGetSymbolAddress((void**)&h2, g_h2);
    float* pr; cudaGetSymbolAddress((void**)&pr, g_prim);
    __half* pd; cudaGetSymbolAddress((void**)&pd, g_pred);
    char* Ah; cudaGetSymbolAddress((void**)&Ah, g_Ahi);
    char* Wh; cudaGetSymbolAddress((void**)&Wh, g_Whi);

    const int RSMEM = 30720 * 4 + 32;     // 122912 B
    cudaFuncSetAttribute(routing_kernel, cudaFuncAttributeMaxDynamicSharedMemorySize, RSMEM);
    const int GSMEM = 1024 + 3 * STGB;    // 99328 B
    cudaFuncSetAttribute(gemm1_mma, cudaFuncAttributeMaxDynamicSharedMemorySize, GSMEM);

    splitA<<<dim3((KP / 8 + 255) / 256, BATCH), 256>>>(features, Ah);
    splitW<<<dim3(KP / 32, H1DIM / 32), 256>>>(W1, Wh);
    gemm1_mma<<<dim3(H1DIM / 128, BATCH / 128), 256, GSMEM>>>(Ah, Wh, b1, h1);
    gemm2_64<<<dim3(256 / 128, 4096 / 64), 256>>>(h1, W2, b2, h2, 4096, 256, 512);
    prim_kernel<<<512, 256>>>(h2, ln_g, ln_b, pc_W, pc_b, pc_g, pc_beta, pr);
    pred_kernel<<<BATCH / 32, 256>>>(pr, dc_W, pd);
    routing_kernel<<<4096, 1024, RSMEM>>>(pd, slot_f, priors, targets, temp, out);
}

// round 16
// speedup vs baseline: 1.6809x; 1.1311x over previous
#include <cuda_runtime.h>
#include <cuda_fp16.h>
#include <math.h>
#include <stdint.h>

#define BATCH  4096
#define IN_DIM 20000
#define H1DIM  512
#define H2DIM  256
#define NCAPS  32
#define PDIM   8
#define CDIM   16
#define NLAB   100

#define KP     20032            // IN_DIM padded to 313*64
#define NCH    313              // chunks
#define TILEB  16384            // one tile: 128 rows x 128 B (swizzled), contiguous
#define STGB   (2 * TILEB)      // stage: A, W
#define NPRED  51200            // 32*100*16 per item

__device__ float g_h1[BATCH * H1DIM];
__device__ float g_h2[BATCH * H2DIM];
__device__ float g_prim[BATCH * NCAPS * PDIM];
__device__ __half g_pred[(size_t)BATCH * NPRED];
// tiled, pre-swizzled fp16 buffers
__device__ __align__(128) char g_Ahi[(size_t)32 * NCH * TILEB];
__device__ __align__(128) char g_Whi[(size_t)4 * NCH * TILEB];

// ---------------- helpers ----------------
__device__ __forceinline__ uint32_t smem_u32(const void* p) {
    uint32_t a;
    asm("{ .reg .u64 t; cvta.to.shared.u64 t, %1; cvt.u32.u64 %0, t; }" : "=r"(a) : "l"(p));
    return a;
}
__device__ __forceinline__ uint32_t sw128(uint32_t off) {
    return off ^ ((off >> 3) & 0x70);
}
__device__ __forceinline__ void ldm_x4(uint32_t* r, uint32_t addr) {
    asm volatile("ldmatrix.sync.aligned.m8n8.x4.shared.b16 {%0,%1,%2,%3}, [%4];"
                 : "=r"(r[0]), "=r"(r[1]), "=r"(r[2]), "=r"(r[3]) : "r"(addr));
}
__device__ __forceinline__ void mma_f16(float* c, const uint32_t* a, const uint32_t* b) {
    asm volatile("mma.sync.aligned.m16n8k16.row.col.f32.f16.f16.f32 "
                 "{%0,%1,%2,%3}, {%4,%5,%6,%7}, {%8,%9}, {%0,%1,%2,%3};"
                 : "+f"(c[0]), "+f"(c[1]), "+f"(c[2]), "+f"(c[3])
                 : "r"(a[0]), "r"(a[1]), "r"(a[2]), "r"(a[3]), "r"(b[0]), "r"(b[1]));
}
__device__ __forceinline__ uint32_t pack_h2(__half a, __half b) {
    __half2 t; t.x = a; t.y = b;
    return *(uint32_t*)&t;
}
// f32x2 packed FMA helpers
__device__ __forceinline__ unsigned long long dup2(float x) {
    unsigned long long r; asm("mov.b64 %0, {%1, %1};" : "=l"(r) : "f"(x)); return r;
}
__device__ __forceinline__ unsigned long long pack2(float a, float b) {
    unsigned long long r; asm("mov.b64 %0, {%1, %2};" : "=l"(r) : "f"(a), "f"(b)); return r;
}
__device__ __forceinline__ void fma2(unsigned long long& d, unsigned long long a, unsigned long long b) {
    asm("fma.rn.f32x2 %0, %1, %2, %0;" : "+l"(d) : "l"(a), "l"(b));
}
__device__ __forceinline__ void unp2(unsigned long long v, float& lo, float& hi) {
    asm("mov.b64 {%0, %1}, %2;" : "=f"(lo), "=f"(hi) : "l"(v));
}
#define MBAR_INIT(a, c) asm volatile("mbarrier.init.shared.b64 [%0], %1;" :: "r"(a), "r"(c) : "memory")
#define MBAR_EXPECT_TX(a, b) asm volatile("mbarrier.arrive.expect_tx.shared.b64 _, [%0], %1;" :: "r"(a), "r"(b) : "memory")
#define BULK_G2S(dst, src, sz, mbar) \
    asm volatile("cp.async.bulk.shared::cluster.global.mbarrier::complete_tx::bytes [%0], [%1], %2, [%3];" \
                 :: "r"(dst), "l"(src), "r"(sz), "r"(mbar) : "memory")

#define MBAR_WAIT(mbar_smem_addr, phase_parity) do { \
    uint32_t _mbar = (uint32_t)(mbar_smem_addr); \
    uint32_t _parity = (uint32_t)(phase_parity); \
    uint32_t _done; \
    asm volatile( \
        "{\n\t.reg .pred p;\n\t" \
        "mbarrier.try_wait.parity.acquire.cta.shared::cta.b64 p, [%1], %2;\n\t" \
        "selp.b32 %0, 1, 0, p;\n\t}" \
        : "=r"(_done) : "r"(_mbar), "r"(_parity) : "memory"); \
    if (!_done) { \
        asm volatile( \
            "{\n\t.reg .pred P1;\n\t" \
            "WAIT_LOOP_%=:\n\t" \
            "mbarrier.try_wait.parity.acquire.cta.shared::cta.b64 P1, [%0], %1, 0x989680;\n\t" \
            "@P1 bra.uni WAIT_DONE_%=;\n\t" \
            "bra.uni WAIT_LOOP_%=;\n\t" \
            "WAIT_DONE_%=:\n\t}" \
            :: "r"(_mbar), "r"(_parity) : "memory"); \
    } \
} while(0)

// ---------------- prep: features -> tiled swizzled fp16 --------------------
__global__ void __launch_bounds__(256)
splitA(const float* __restrict__ F, char* __restrict__ Ah) {
    int m = blockIdx.y;
    int u = blockIdx.x * 256 + threadIdx.x;
    if (u >= KP / 8) return;
    int k0 = u * 8;
    float v[8];
    if (k0 < IN_DIM) {
        const float4* fp = (const float4*)(F + (size_t)m * IN_DIM + k0);
        float4 f0 = fp[0], f1 = fp[1];
        v[0]=f0.x; v[1]=f0.y; v[2]=f0.z; v[3]=f0.w;
        v[4]=f1.x; v[5]=f1.y; v[6]=f1.z; v[7]=f1.w;
    } else {
#pragma unroll
        for (int j = 0; j < 8; j++) v[j] = 0.f;
    }
    uint32_t hi[4];
#pragma unroll
    for (int j = 0; j < 4; j++)
        hi[j] = pack_h2(__float2half_rn(v[2*j]), __float2half_rn(v[2*j+1]));
    int mt = m >> 7, row = m & 127, ch = u >> 3, u8 = u & 7;
    uint32_t off = sw128((uint32_t)(row * 128 + u8 * 16));
    size_t addr = ((size_t)mt * NCH + ch) * TILEB + off;
    *(uint4*)(Ah + addr) = make_uint4(hi[0], hi[1], hi[2], hi[3]);
}

// ---------------- prep: transpose W1 [K,N] -> tiled swizzled fp16 ----------
__global__ void __launch_bounds__(256)
splitW(const float* __restrict__ W1, char* __restrict__ Wh) {
    __shared__ float ts[32][33];
    int k0 = blockIdx.x * 32, n0 = blockIdx.y * 32;
    int tx = threadIdx.x & 31, ty = threadIdx.x >> 5;
#pragma unroll
    for (int r = 0; r < 32; r += 8) {
        int k = k0 + ty + r;
        ts[ty + r][tx] = (k < IN_DIM) ? W1[(size_t)k * H1DIM + n0 + tx] : 0.f;
    }
    __syncthreads();
#pragma unroll
    for (int r = 0; r < 32; r += 8) {
        int n = n0 + ty + r;
        int k = k0 + tx;
        float x = ts[tx][ty + r];
        int nt = n >> 7, row = n & 127, ch = k >> 6, kk = k & 63;
        uint32_t off = sw128((uint32_t)(row * 128 + kk * 2));
        size_t addr = ((size_t)nt * NCH + ch) * TILEB + off;
        *(__half*)(Wh + addr) = __float2half_rn(x);
    }
}

// ---------------- GEMM1: 3-stage bulk-TMA + mma.sync fp16 ------------------
__global__ void __launch_bounds__(256)
gemm1_mma(const char* __restrict__ Ath, const char* __restrict__ Wth,
          const float* __restrict__ bias, float* __restrict__ C) {
    extern __shared__ __align__(1024) char smem[];
    const uint32_t sb = smem_u32(smem);
    const uint32_t mb0 = sb, mb1 = sb + 8, mb2 = sb + 16;
    const uint32_t stage0 = sb + 1024;
    const int tid = threadIdx.x;
    const int lane = tid & 31, wid = tid >> 5;
    const int wm = wid & 3, wn = wid >> 2;
    const int m0 = blockIdx.y * 128, n0 = blockIdx.x * 128;

    const char* srcs[2] = {
        Ath + (size_t)blockIdx.y * NCH * TILEB,
        Wth + (size_t)blockIdx.x * NCH * TILEB
    };

    if (tid == 0) { MBAR_INIT(mb0, 1u); MBAR_INIT(mb1, 1u); MBAR_INIT(mb2, 1u); }
    __syncthreads();

    const int aq = lane >> 3;
    const uint32_t a_row = (uint32_t)((aq & 1) * 8 + (lane & 7));
    const uint32_t a_colb = (uint32_t)((aq >> 1) * 16);
    const uint32_t b_row = (uint32_t)(((aq & 2) ? 8 : 0) + (lane & 7));
    const uint32_t b_colb = (uint32_t)((aq & 1) * 16);

    float acc[2][8][4];
#pragma unroll
    for (int mt = 0; mt < 2; mt++)
#pragma unroll
        for (int nt = 0; nt < 8; nt++)
#pragma unroll
            for (int e = 0; e < 4; e++) acc[mt][nt][e] = 0.f;

    if (tid == 0) {
#pragma unroll
        for (int c = 0; c < 2; c++) {
            uint32_t mbc = sb + 8u * c;
            MBAR_EXPECT_TX(mbc, (uint32_t)STGB);
#pragma unroll
            for (int p = 0; p < 2; p++)
                BULK_G2S(stage0 + c * STGB + p * TILEB, srcs[p] + (size_t)c * TILEB,
                         (uint32_t)TILEB, mbc);
        }
    }

    int s = 0, ph0 = 0, ph1 = 0, ph2v = 0;
    for (int t = 0; t < NCH; ++t) {
        if (t + 2 < NCH && tid == 0) {
            int s2 = s + 2; if (s2 >= 3) s2 -= 3;
            uint32_t mbn = sb + 8u * s2;
            uint32_t stn = stage0 + (uint32_t)(s2 * STGB);
            MBAR_EXPECT_TX(mbn, (uint32_t)STGB);
#pragma unroll
            for (int p = 0; p < 2; p++)
                BULK_G2S(stn + p * TILEB, srcs[p] + (size_t)(t + 2) * TILEB,
                         (uint32_t)TILEB, mbn);
        }
        if (s == 0)      { MBAR_WAIT(mb0, ph0); ph0 ^= 1; }
        else if (s == 1) { MBAR_WAIT(mb1, ph1); ph1 ^= 1; }
        else             { MBAR_WAIT(mb2, ph2v); ph2v ^= 1; }

        const uint32_t st = stage0 + (uint32_t)(s * STGB);
        const uint32_t aRow = (uint32_t)(wm * 32) + a_row;
        const uint32_t bRow = (uint32_t)(wn * 64) + b_row;

#pragma unroll
        for (int ks = 0; ks < 4; ++ks) {
            const uint32_t kb = (uint32_t)(ks * 32);
            uint32_t ah[2][4];
#pragma unroll
            for (int mt = 0; mt < 2; mt++) {
                uint32_t off = sw128((aRow + mt * 16) * 128 + kb + a_colb);
                ldm_x4(ah[mt], st + 0 * TILEB + off);
            }
            uint32_t bh[8][2];
#pragma unroll
            for (int np = 0; np < 4; np++) {
                uint32_t off = sw128((bRow + np * 16) * 128 + kb + b_colb);
                uint32_t rh[4];
                ldm_x4(rh, st + 1 * TILEB + off);
                bh[np * 2][0] = rh[0]; bh[np * 2][1] = rh[1];
                bh[np * 2 + 1][0] = rh[2]; bh[np * 2 + 1][1] = rh[3];
            }
#pragma unroll
            for (int mt = 0; mt < 2; mt++)
#pragma unroll
                for (int nt = 0; nt < 8; nt++)
                    mma_f16(acc[mt][nt], ah[mt], bh[nt]);
        }
        __syncthreads();
        s = (s + 1 == 3) ? 0 : s + 1;
    }

    const int l4 = lane >> 2, l2 = (lane & 3) * 2;
    const int ncol0 = n0 + wn * 64;
#pragma unroll
    for (int mt = 0; mt < 2; mt++) {
        int m = m0 + wm * 32 + mt * 16 + l4;
        float* r0 = C + (size_t)m * H1DIM + ncol0;
        float* r1 = r0 + (size_t)8 * H1DIM;
#pragma unroll
        for (int nt = 0; nt < 8; nt++) {
            int col = nt * 8 + l2;
            float b0 = bias[ncol0 + col], b1 = bias[ncol0 + col + 1];
            float v0 = fmaxf(acc[mt][nt][0] + b0, 0.f);
            float v1 = fmaxf(acc[mt][nt][1] + b1, 0.f);
            float v2 = fmaxf(acc[mt][nt][2] + b0, 0.f);
            float v3 = fmaxf(acc[mt][nt][3] + b1, 0.f);
            *(float2*)&r0[col] = make_float2(v0, v1);
            *(float2*)&r1[col] = make_float2(v2, v3);
        }
    }
}

// -------- GEMM2 (fp32): BM=64, C = relu(A@B + b) -----
__global__ void __launch_bounds__(256)
gemm2_64(const float* __restrict__ A, const float* __restrict__ B,
         const float* __restrict__ bias, float* __restrict__ C,
         int M, int N, int K) {
    const int BKf = 16;
    __shared__ __align__(16) float As[2][16][72];
    __shared__ __align__(16) float Bs[2][16][128];

    const int tid = threadIdx.x;
    const int tx = tid & 15, ty = tid >> 4;
    const int m0 = blockIdx.y * 64, n0 = blockIdx.x * 128;
    const int ar0 = tid >> 2, ak0 = (tid & 3) * 4;
    const int br0 = tid >> 5, bc0 = (tid & 31) * 4;

    const float* Aptr = A + (size_t)(m0 + ar0) * K + ak0;
    const float* Bptr = B + (size_t)br0 * N + n0 + bc0;

    unsigned long long acc[4][4];
#pragma unroll
    for (int i = 0; i < 4; i++)
#pragma unroll
        for (int j = 0; j < 4; j++) acc[i][j] = 0ull;

    float4 a0f = *(const float4*)Aptr;
    float4 b0f = *(const float4*)Bptr;
    float4 b1f = *(const float4*)(Bptr + 8 * N);

    As[0][ak0+0][ar0] = a0f.x; As[0][ak0+1][ar0] = a0f.y;
    As[0][ak0+2][ar0] = a0f.z; As[0][ak0+3][ar0] = a0f.w;
    *(float4*)&Bs[0][br0][bc0] = b0f;
    *(float4*)&Bs[0][br0+8][bc0] = b1f;
    __syncthreads();

    const int nT = K / BKf;
    int buf = 0;
    for (int t = 0; t < nT; ++t) {
        if (t + 1 < nT) {
            a0f = *(const float4*)(Aptr + (t + 1) * BKf);
            const float* Bp = Bptr + (size_t)(t + 1) * BKf * N;
            b0f = *(const float4*)Bp;
            b1f = *(const float4*)(Bp + 8 * N);
        }
#pragma unroll
        for (int k = 0; k < BKf; ++k) {
            float4 av = *(const float4*)&As[buf][k][ty * 4];
            ulonglong2 bA = *(const ulonglong2*)&Bs[buf][k][tx * 8];
            ulonglong2 bB = *(const ulonglong2*)&Bs[buf][k][tx * 8 + 4];
            float avf[4] = {av.x, av.y, av.z, av.w};
#pragma unroll
            for (int i = 0; i < 4; i++) {
                unsigned long long ad = dup2(avf[i]);
                fma2(acc[i][0], ad, bA.x);
                fma2(acc[i][1], ad, bA.y);
                fma2(acc[i][2], ad, bB.x);
                fma2(acc[i][3], ad, bB.y);
            }
        }
        if (t + 1 < nT) {
            int nb = buf ^ 1;
            As[nb][ak0+0][ar0] = a0f.x; As[nb][ak0+1][ar0] = a0f.y;
            As[nb][ak0+2][ar0] = a0f.z; As[nb][ak0+3][ar0] = a0f.w;
            *(float4*)&Bs[nb][br0][bc0] = b0f;
            *(float4*)&Bs[nb][br0+8][bc0] = b1f;
        }
        __syncthreads();
        buf ^= 1;
    }

    float bb[8];
#pragma unroll
    for (int c = 0; c < 8; c++) bb[c] = bias[n0 + tx * 8 + c];
#pragma unroll
    for (int i = 0; i < 4; i++) {
        float* Crow = C + (size_t)(m0 + ty * 4 + i) * N + n0 + tx * 8;
#pragma unroll
        for (int j = 0; j < 4; j++) {
            float lo, hi; unp2(acc[i][j], lo, hi);
            lo = fmaxf(lo + bb[2*j], 0.f);
            hi = fmaxf(hi + bb[2*j+1], 0.f);
            *(float2*)&Crow[2*j] = make_float2(lo, hi);
        }
    }
}

// -------- primary caps: fused row-LN + einsum + bias + per-capsule LN ------
__global__ void __launch_bounds__(256)
prim_kernel(const float* __restrict__ h2, const float* __restrict__ lng,
            const float* __restrict__ lnb, const float* __restrict__ pcW,
            const float* __restrict__ pcB, const float* __restrict__ pcG,
            const float* __restrict__ pcBeta, float* __restrict__ prim) {
    __shared__ float hs[8 * 256];
    int tid = threadIdx.x;
    int row0 = blockIdx.x * 8;
    for (int i = tid; i < 2048; i += 256) hs[i] = h2[(size_t)row0 * 256 + i];
    __syncthreads();

    {
        int warp = tid >> 5, lane = tid & 31;
        float* xr = hs + warp * 256;
        float x[8];
#pragma unroll
        for (int e = 0; e < 8; e++) x[e] = xr[lane + 32 * e];
        float s = 0.f;
#pragma unroll
        for (int e = 0; e < 8; e++) s += x[e];
#pragma unroll
        for (int o = 16; o; o >>= 1) s += __shfl_xor_sync(~0u, s, o);
        float mu = s * (1.f / 256.f);
        float vs = 0.f;
#pragma unroll
        for (int e = 0; e < 8; e++) { float d = x[e] - mu; vs += d * d; }
#pragma unroll
        for (int o = 16; o; o >>= 1) vs += __shfl_xor_sync(~0u, vs, o);
        float inv = rsqrtf(vs * (1.f / 256.f) + 1e-5f);
#pragma unroll
        for (int e = 0; e < 8; e++) {
            int c = lane + 32 * e;
            xr[c] = (x[e] - mu) * inv * lng[c] + lnb[c];
        }
    }
    __syncthreads();

    int n = tid >> 3;
    float acc[8] = {0,0,0,0,0,0,0,0};
    const float* w = pcW + n * 2048 + (tid & 7);
    for (int c = 0; c < 256; c += 4) {
        float w0 = w[(c+0)*8], w1 = w[(c+1)*8], w2 = w[(c+2)*8], w3 = w[(c+3)*8];
#pragma unroll
        for (int r = 0; r < 8; r++)
            acc[r] += hs[r*256+c]*w0 + hs[r*256+c+1]*w1 + hs[r*256+c+2]*w2 + hs[r*256+c+3]*w3;
    }
    float bn = pcB[tid], gg = pcG[tid], bt = pcBeta[tid];
#pragma unroll
    for (int r = 0; r < 8; r++) {
        float x = acc[r] + bn;
        float s = x;
        s += __shfl_xor_sync(~0u, s, 1); s += __shfl_xor_sync(~0u, s, 2); s += __shfl_xor_sync(~0u, s, 4);
        float mu = s * 0.125f;
        float dv = x - mu;
        float v = dv * dv;
        v += __shfl_xor_sync(~0u, v, 1); v += __shfl_xor_sync(~0u, v, 2); v += __shfl_xor_sync(~0u, v, 4);
        float inv = rsqrtf(v * 0.125f + 1e-5f);
        prim[(size_t)(row0 + r) * 256 + tid] = dv * inv * gg + bt;
    }
}

// -------- predictions GEMM: 32 items/CTA, packed f32x2 FMA, fp16 out -------
__global__ void __launch_bounds__(256)
pred_kernel(const float* __restrict__ prim, const float* __restrict__ dcW,
            __half* __restrict__ pred) {
    __shared__ float ps[32 * 256];
    const int tid = threadIdx.x;
    const int m0 = blockIdx.x * 32;
    for (int i = tid; i < 32 * 256 / 4; i += 256)
        ((float4*)ps)[i] = ((const float4*)(prim + (size_t)m0 * 256))[i];
    __syncthreads();

    for (int eg = 0; eg < 25; eg++) {
        int e8 = tid + eg * 256;
        int e = e8 * 8;
        int n = e / 1600;
        const float4* wp = (const float4*)(dcW + (size_t)e * 8);
        // pre-packed coefficient pairs: pk[pr][k] pairs rows (2pr, 2pr+1)
        unsigned long long pk[4][8];
#pragma unroll
        for (int pr = 0; pr < 4; pr++) {
            float4 wa0 = wp[4*pr + 0];   // coeffs of r[2pr]   vs pa
            float4 wb0 = wp[4*pr + 1];   // coeffs of r[2pr]   vs pb
            float4 wa1 = wp[4*pr + 2];   // coeffs of r[2pr+1] vs pa
            float4 wb1 = wp[4*pr + 3];   // coeffs of r[2pr+1] vs pb
            pk[pr][0] = pack2(wa0.x, wa1.x);
            pk[pr][1] = pack2(wa0.y, wa1.y);
            pk[pr][2] = pack2(wa0.z, wa1.z);
            pk[pr][3] = pack2(wa0.w, wa1.w);
            pk[pr][4] = pack2(wb0.x, wb1.x);
            pk[pr][5] = pack2(wb0.y, wb1.y);
            pk[pr][6] = pack2(wb0.z, wb1.z);
            pk[pr][7] = pack2(wb0.w, wb1.w);
        }
#pragma unroll 2
        for (int i = 0; i < 32; i++) {
            const float* p = ps + i * 256 + n * 8;
            float4 pa = *(const float4*)p;
            float4 pb = *(const float4*)(p + 4);
            unsigned long long acc[4] = {0ull, 0ull, 0ull, 0ull};
            float pav[4] = {pa.x, pa.y, pa.z, pa.w};
            float pbv[4] = {pb.x, pb.y, pb.z, pb.w};
#pragma unroll
            for (int k = 0; k < 4; k++) {
                unsigned long long d = dup2(pav[k]);
#pragma unroll
                for (int pr = 0; pr < 4; pr++) fma2(acc[pr], pk[pr][k], d);
            }
#pragma unroll
            for (int k = 0; k < 4; k++) {
                unsigned long long d = dup2(pbv[k]);
#pragma unroll
                for (int pr = 0; pr < 4; pr++) fma2(acc[pr], pk[pr][k + 4], d);
            }
            float r[8];
#pragma unroll
            for (int pr = 0; pr < 4; pr++) unp2(acc[pr], r[2*pr], r[2*pr+1]);
            __half2 h0 = __floats2half2_rn(r[0], r[1]);
            __half2 h1 = __floats2half2_rn(r[2], r[3]);
            __half2 h2v = __floats2half2_rn(r[4], r[5]);
            __half2 h3 = __floats2half2_rn(r[6], r[7]);
            uint4 u;
            u.x = *(uint32_t*)&h0; u.y = *(uint32_t*)&h1;
            u.z = *(uint32_t*)&h2v; u.w = *(uint32_t*)&h3;
            *(uint4*)(pred + (size_t)(m0 + i) * NPRED + e) = u;
        }
    }
}

// -------- fused routing + logits; fp16 pred via bulk copy ------------------
// vv padded to 20 floats/row for conflict-free float4 loads
__global__ void __launch_bounds__(1024)
routing_kernel(const __half* __restrict__ pred_g,
               const float* __restrict__ sf, const float* __restrict__ priors,
               const float* __restrict__ targets, const float* __restrict__ temp_p,
               float* __restrict__ out) {
    extern __shared__ float sm[];
    __half2* ph2 = (__half2*)sm;        // 25600 half2 = 25600 float slots
    float* bq   = sm + 25600;           // 3200
    float* vv   = bq + 3200;            // 2000 (100 x 20 padded)
    float* sp   = vv + 2000;            // 128
    float* mrow = sp + 128;             // 32
    float* lse  = mrow + 32;            // 32
    float* red  = lse + 32;             // 128
    const uint32_t mbar = smem_u32(sm) + 31120u * 4u;

    const int bidx = blockIdx.x;
    const int tid = threadIdx.x;
    const int lane = tid & 31, warp = tid >> 5;

    if (tid == 0) MBAR_INIT(mbar, 1u);
    __syncthreads();
    if (tid == 0) {
        MBAR_EXPECT_TX(mbar, (uint32_t)(NPRED * 2));
        const char* src = (const char*)(pred_g + (size_t)bidx * NPRED);
        uint32_t dst = smem_u32(sm);
#pragma unroll
        for (int p = 0; p < 4; p++)
            BULK_G2S(dst + p * (NPRED / 2), src + (size_t)p * (NPRED / 2),
                     (uint32_t)(NPRED / 2), mbar);
    }

    if (tid < 100) red[tid] = fmaxf(sf[(size_t)bidx * 100 + tid], 0.f);
    __syncthreads();
    if (tid < 32) {
        float s = red[tid] + red[tid + 32] + red[tid + 64] + ((tid < 4) ? red[tid + 96] : 0.f);
#pragma unroll
        for (int o = 16; o; o >>= 1) s += __shfl_xor_sync(~0u, s, o);
        if (tid == 0) red[112] = s;
    }
    __syncthreads();
    float invs = 1.f / fmaxf(red[112], 1e-6f);
    __syncthreads();
    if (tid < 100) red[tid] = red[tid] * invs - 0.01f;
    __syncthreads();
    if (tid < 100) {
        float a = 0.f;
        for (int s = 0; s < 100; s++) a += red[s] * priors[s * 100 + tid];
        sp[tid] = a;
    }
    __syncthreads();

    for (int idx = tid; idx < 3200; idx += 1024) bq[idx] = sp[idx % 100] * 0.1f;

    MBAR_WAIT(mbar, 0);
    __syncthreads();

    for (int it = 0; it < 3; it++) {
        {
            float b0 = bq[warp * 100 + lane];
            float b1 = bq[warp * 100 + 32 + lane];
            float b2 = bq[warp * 100 + 64 + lane];
            float b3 = (lane < 4) ? bq[warp * 100 + 96 + lane] : -1e30f;
            float m = fmaxf(fmaxf(b0, b1), fmaxf(b2, b3));
#pragma unroll
            for (int o = 16; o; o >>= 1) m = fmaxf(m, __shfl_xor_sync(~0u, m, o));
            float e0 = __expf(b0 - m), e1 = __expf(b1 - m), e2 = __expf(b2 - m);
            float e3 = (lane < 4) ? __expf(b3 - m) : 0.f;
            float s = e0 + e1 + e2 + e3;
#pragma unroll
            for (int o = 16; o; o >>= 1) s += __shfl_xor_sync(~0u, s, o);
            float is = 1.f / s;
            bq[warp * 100 + lane]      = e0 * is;
            bq[warp * 100 + 32 + lane] = e1 * is;
            bq[warp * 100 + 64 + lane] = e2 * is;
            if (lane < 4) bq[warp * 100 + 96 + lane] = e3 * is;
            if (lane == 0) { mrow[warp] = m; lse[warp] = __logf(s); }
        }
        __syncthreads();

        // s[j,o-pair] over 800 half2 items
        if (tid < 800) {
            int j = tid >> 3;
            float s0 = 0.f, s1 = 0.f;
#pragma unroll 8
            for (int n = 0; n < 32; n++) {
                float c = bq[n * 100 + j];
                float2 p = __half22float2(ph2[n * 800 + tid]);
                s0 += c * p.x; s1 += c * p.y;
            }
            int o2 = (tid & 7) * 2;
            vv[j * 20 + o2] = s0;
            vv[j * 20 + o2 + 1] = s1;
        }
        __syncthreads();
        if (tid < 100) {
            float sq = 0.f;
#pragma unroll
            for (int o = 0; o < 16; o++) { float t = vv[tid * 20 + o]; sq += t * t; }
            red[tid] = (sq / (1.f + sq)) * rsqrtf(sq + 1e-8f);
        }
        __syncthreads();
        for (int idx = tid; idx < 1600; idx += 1024)
            vv[(idx >> 4) * 20 + (idx & 15)] *= red[idx >> 4];
        __syncthreads();

        if (it < 2) {
            float strength = 0.1f - 0.02f * (it + 1);
            if (tid < 1000) {
                int sl = tid / 100;          // n-slice 0..9
                int j  = tid % 100;          // consecutive lanes -> consecutive j
                float4 v0 = *(const float4*)&vv[j * 20 + 0];
                float4 v1 = *(const float4*)&vv[j * 20 + 4];
                float4 v2 = *(const float4*)&vv[j * 20 + 8];
                float4 v3 = *(const float4*)&vv[j * 20 + 12];
                float spj = sp[j] * strength;
                for (int n = sl; n < 32; n += 10) {
                    const uint4* pp = (const uint4*)(ph2 + n * 800 + j * 8);
                    uint4 q0 = pp[0], q1 = pp[1];
                    float dot = 0.f;
                    float2 p;
                    p = __half22float2(((__half2*)&q0)[0]); dot += p.x*v0.x + p.y*v0.y;
                    p = __half22float2(((__half2*)&q0)[1]); dot += p.x*v0.z + p.y*v0.w;
                    p = __half22float2(((__half2*)&q0)[2]); dot += p.x*v1.x + p.y*v1.y;
                    p = __half22float2(((__half2*)&q0)[3]); dot += p.x*v1.z + p.y*v1.w;
                    p = __half22float2(((__half2*)&q1)[0]); dot += p.x*v2.x + p.y*v2.y;
                    p = __half22float2(((__half2*)&q1)[1]); dot += p.x*v2.z + p.y*v2.w;
                    p = __half22float2(((__half2*)&q1)[2]); dot += p.x*v3.x + p.y*v3.y;
                    p = __half22float2(((__half2*)&q1)[3]); dot += p.x*v3.z + p.y*v3.w;
                    float c = bq[n * 100 + j];
                    bq[n * 100 + j] = __logf(fmaxf(c, 1e-38f)) + mrow[n] + lse[n] + dot + spj;
                }
            }
            __syncthreads();
        }
    }

    if (tid < 100) {
        float nr = 0.f, dt = 0.f;
#pragma unroll
        for (int o = 0; o < 16; o++) {
            float v = vv[tid * 20 + o];
            nr += v * v;
            dt += v * targets[tid * 16 + o];
        }
        out[(size_t)bidx * 100 + tid] = temp_p[0] * dt / fmaxf(sqrtf(nr), 1e-12f);
    }
}

extern "C" void kernel_launch(void* const* d_in, const int* in_sizes, int n_in,
                              void* d_out, int out_size) {
    const float* features = (const float*)d_in[0];
    const float* slot_f   = (const float*)d_in[1];
    const float* W1       = (const float*)d_in[2];
    const float* b1       = (const float*)d_in[3];
    const float* W2       = (const float*)d_in[4];
    const float* b2       = (const float*)d_in[5];
    const float* ln_g     = (const float*)d_in[6];
    const float* ln_b     = (const float*)d_in[7];
    const float* pc_W     = (const float*)d_in[8];
    const float* pc_b     = (const float*)d_in[9];
    const float* pc_g     = (const float*)d_in[10];
    const float* pc_beta  = (const float*)d_in[11];
    const float* dc_W     = (const float*)d_in[12];
    const float* priors   = (const float*)d_in[13];
    const float* targets  = (const float*)d_in[14];
    const float* temp     = (const float*)d_in[15];
    float* out = (float*)d_out;

    float* h1; cudaGetSymbolAddress((void**)&h1, g_h1);
    float* h2; cudaGetSymbolAddress((void**)&h2, g_h2);
    float* pr; cudaGetSymbolAddress((void**)&pr, g_prim);
    __half* pd; cudaGetSymbolAddress((void**)&pd, g_pred);
    char* Ah; cudaGetSymbolAddress((void**)&Ah, g_Ahi);
    char* Wh; cudaGetSymbolAddress((void**)&Wh, g_Whi);

    const int RSMEM = 31120 * 4 + 32;     // 124512 B
    cudaFuncSetAttribute(routing_kernel, cudaFuncAttributeMaxDynamicSharedMemorySize, RSMEM);
    const int GSMEM = 1024 + 3 * STGB;    // 99328 B
    cudaFuncSetAttribute(gemm1_mma, cudaFuncAttributeMaxDynamicSharedMemorySize, GSMEM);

    splitA<<<dim3((KP / 8 + 255) / 256, BATCH), 256>>>(features, Ah);
    splitW<<<dim3(KP / 32, H1DIM / 32), 256>>>(W1, Wh);
    gemm1_mma<<<dim3(H1DIM / 128, BATCH / 128), 256, GSMEM>>>(Ah, Wh, b1, h1);
    gemm2_64<<<dim3(256 / 128, 4096 / 64), 256>>>(h1, W2, b2, h2, 4096, 256, 512);
    prim_kernel<<<512, 256>>>(h2, ln_g, ln_b, pc_W, pc_b, pc_g, pc_beta, pr);
    pred_kernel<<<BATCH / 32, 256>>>(pr, dc_W, pd);
    routing_kernel<<<4096, 1024, RSMEM>>>(pd, slot_f, priors, targets, temp, out);
}